// round 1
// baseline (speedup 1.0000x reference)
#include <cuda_runtime.h>

// Problem constants (fixed by the dataset reference)
#define BB   8
#define NN   2048
#define CC   16
#define HID  128
#define RFN  16384      // 128*128 receptive fields
#define KTOT 144        // C + HID
#define GATES 512       // 4*HID
#define OUT_ELEMS (BB*HID*128*128)

// ---------------- device scratch (no allocations allowed) ----------------
__device__ int   g_rf[BB*NN];
__device__ int   g_rank[BB*NN];
__device__ int   g_count[BB*RFN];
__device__ int   g_offset[BB*RFN];
__device__ int   g_sorted[BB*NN];
__device__ int   g_hist[NN+1];
__device__ int   g_base[NN+1];
__device__ int   g_cursor[NN+1];
__device__ int   g_nactive;
__device__ int4  g_chains[BB*NN];       // {b, rf, offset, len}
__device__ float g_WT[KTOT*GATES];      // transposed [k][g]; rows 0..15 = w_ih, 16..143 = w_hh
__device__ float g_bias[GATES];

// ---------------- helpers ----------------
__device__ __forceinline__ float sigmoidf_(float x) {
    return __fdividef(1.0f, 1.0f + __expf(-x));
}
__device__ __forceinline__ float tanhf_(float x) {
    float ax = fabsf(x);
    float e  = __expf(-2.0f * ax);
    float t  = __fdividef(1.0f - e, 1.0f + e);
    return copysignf(t, x);
}

// K0: zero the 64MB output
__global__ void k_zero_out(float4* __restrict__ out) {
    int i = blockIdx.x * blockDim.x + threadIdx.x;
    if (i < OUT_ELEMS/4) out[i] = make_float4(0.f,0.f,0.f,0.f);
}

// K1: zero scratch that must be fresh every replay
__global__ void k_zero_scratch() {
    int i = blockIdx.x * blockDim.x + threadIdx.x;
    int stride = gridDim.x * blockDim.x;
    for (int t = i; t < BB*RFN; t += stride) g_count[t] = 0;
    for (int t = i; t < NN+1; t += stride) { g_hist[t] = 0; g_cursor[t] = 0; }
    if (i == 0) g_nactive = 0;
}

// K8: build transposed weights + fused bias
__global__ void k_prep_w(const float* __restrict__ w_ih, const float* __restrict__ w_hh,
                         const float* __restrict__ b_ih, const float* __restrict__ b_hh) {
    int t = blockIdx.x * blockDim.x + threadIdx.x;
    if (t < KTOT*GATES) {
        int k = t / GATES, g = t % GATES;
        g_WT[t] = (k < CC) ? w_ih[g*CC + k] : w_hh[g*HID + (k - CC)];
    }
    if (t < GATES) g_bias[t] = b_ih[t] + b_hh[t];
}

// K23: per-batch rf + histogram + stable rank (1 block per batch)
__global__ void k_rf_count_rank(const int* __restrict__ coords) {
    __shared__ int rfsh[NN];
    int b = blockIdx.x;
    int tid = threadIdx.x;
    for (int n = tid; n < NN; n += blockDim.x) {
        int x = coords[(b*NN + n)*2 + 0];
        int y = coords[(b*NN + n)*2 + 1];
        int rf = y * 128 + x;
        rfsh[n] = rf;
        g_rf[b*NN + n] = rf;
        atomicAdd(&g_count[b*RFN + rf], 1);
    }
    __syncthreads();
    for (int n = tid; n < NN; n += blockDim.x) {
        int myrf = rfsh[n];
        int r = 0;
        for (int m = 0; m < n; m++) r += (rfsh[m] == myrf);
        g_rank[b*NN + n] = r;
    }
}

// K4: per-batch exclusive prefix sum of counts (1 block/batch, 1024 thr, 16 bins/thr)
__global__ void k_offsets() {
    __shared__ int ssum[1024];
    int b = blockIdx.x, tid = threadIdx.x;
    int base = b*RFN + tid*16;
    int cs[16];
    int tot = 0;
    #pragma unroll
    for (int i = 0; i < 16; i++) {
        int c = g_count[base + i];
        cs[i] = tot;
        tot += c;
    }
    ssum[tid] = tot;
    __syncthreads();
    for (int d = 1; d < 1024; d <<= 1) {
        int v = (tid >= d) ? ssum[tid - d] : 0;
        __syncthreads();
        ssum[tid] += v;
        __syncthreads();
    }
    int prev = ssum[tid] - tot;
    #pragma unroll
    for (int i = 0; i < 16; i++) g_offset[base + i] = prev + cs[i];
}

// K5: stable scatter of events into chain order + chain-length histogram
__global__ void k_scatter() {
    int t = blockIdx.x * blockDim.x + threadIdx.x;
    if (t >= BB*NN) return;
    int b = t / NN, n = t % NN;
    int rf = g_rf[t];
    int r  = g_rank[t];
    int off = g_offset[b*RFN + rf];
    g_sorted[b*NN + off + r] = n;
    if (r == 0) atomicAdd(&g_hist[g_count[b*RFN + rf]], 1);
}

// K6: length-descending bases + n_active
__global__ void k_bases() {
    __shared__ int h[NN+1];
    int tid = threadIdx.x;
    for (int i = tid; i <= NN; i += blockDim.x) h[i] = g_hist[i];
    __syncthreads();
    if (tid == 0) {
        int run = 0;
        for (int L = NN; L >= 1; L--) { g_base[L] = run; run += h[L]; }
        g_nactive = run;
    }
}

// K7: register chains, grouped by length (longest first)
__global__ void k_chains() {
    int t = blockIdx.x * blockDim.x + threadIdx.x;
    if (t >= BB*NN) return;
    if (g_rank[t] != 0) return;
    int b = t / NN;
    int rf = g_rf[t];
    int cidx = b*RFN + rf;
    int L   = g_count[cidx];
    int off = g_offset[cidx];
    int pos = g_base[L] + atomicAdd(&g_cursor[L], 1);
    g_chains[pos] = make_int4(b, rf, off, L);
}

// K9: main LSTM kernel — 32 chains per block, thread tile = 4 chains x 16 gates
__global__ void __launch_bounds__(256) k_lstm(const float* __restrict__ feat,
                                              float* __restrict__ out) {
    __shared__ float ins[32][KTOT];   // [chain][x(16) | h(128)]
    __shared__ float csh[32][HID];
    __shared__ float bsh[GATES];
    __shared__ int   cb[32], crf[32], coff[32], clen[32], cev[32];
    __shared__ int   smaxlen;

    int tid  = threadIdx.x;
    int lane = tid & 31;
    int warp = tid >> 5;
    int nact = g_nactive;
    int cbase = blockIdx.x * 32;
    if (cbase >= nact) return;

    if (tid < 32) {
        int bb = 0, rr = 0, oo = 0, ll = 0;
        if (cbase + tid < nact) {
            int4 m = g_chains[cbase + tid];
            bb = m.x; rr = m.y; oo = m.z; ll = m.w;
        }
        cb[tid] = bb; crf[tid] = rr; coff[tid] = oo; clen[tid] = ll;
    }
    for (int i = tid; i < GATES; i += 256) bsh[i] = g_bias[i];
    for (int i = tid; i < 32*HID; i += 256) {
        int ch = i >> 7, k = i & 127;
        csh[ch][k] = 0.f;
        ins[ch][CC + k] = 0.f;
    }
    for (int i = tid; i < 32*CC; i += 256) {
        int ch = i >> 4, c = i & 15;
        ins[ch][c] = 0.f;
    }
    __syncthreads();
    if (tid == 0) {
        int m = 0;
        for (int i = 0; i < 32; i++) m = max(m, clen[i]);
        smaxlen = m;
    }
    __syncthreads();
    int maxlen = smaxlen;
    int mych = warp << 2;

    for (int r = 0; r < maxlen; r++) {
        // stage current event index per chain
        if (tid < 32) cev[tid] = (clen[tid] > r) ? g_sorted[cb[tid]*NN + coff[tid] + r] : -1;
        __syncthreads();
        // stage x
        for (int i = tid; i < 32*CC; i += 256) {
            int ch = i >> 4, c = i & 15;
            int e = cev[ch];
            if (e >= 0) ins[ch][c] = feat[(cb[ch]*NN + e)*CC + c];
        }
        __syncthreads();

        // gates = bias + [x|h] @ W_T   (step 0: h == 0 -> only K=16 needed)
        float acc[4][16];
        #pragma unroll
        for (int q = 0; q < 4; q++) {
            float4 bv = *(const float4*)&bsh[q*128 + (lane << 2)];
            #pragma unroll
            for (int c = 0; c < 4; c++) {
                acc[c][q*4+0] = bv.x; acc[c][q*4+1] = bv.y;
                acc[c][q*4+2] = bv.z; acc[c][q*4+3] = bv.w;
            }
        }
        int kend = (r == 0) ? CC : KTOT;
        #pragma unroll 4
        for (int k = 0; k < kend; k++) {
            const float* wk = g_WT + k*GATES + (lane << 2);
            float4 w0 = *(const float4*)(wk);
            float4 w1 = *(const float4*)(wk + 128);
            float4 w2 = *(const float4*)(wk + 256);
            float4 w3 = *(const float4*)(wk + 384);
            #pragma unroll
            for (int c = 0; c < 4; c++) {
                float iv = ins[mych + c][k];
                acc[c][0]  += iv*w0.x; acc[c][1]  += iv*w0.y; acc[c][2]  += iv*w0.z; acc[c][3]  += iv*w0.w;
                acc[c][4]  += iv*w1.x; acc[c][5]  += iv*w1.y; acc[c][6]  += iv*w1.z; acc[c][7]  += iv*w1.w;
                acc[c][8]  += iv*w2.x; acc[c][9]  += iv*w2.y; acc[c][10] += iv*w2.z; acc[c][11] += iv*w2.w;
                acc[c][12] += iv*w3.x; acc[c][13] += iv*w3.y; acc[c][14] += iv*w3.z; acc[c][15] += iv*w3.w;
            }
        }
        __syncthreads();  // all reads of ins/h done before state update

        // activations + state update (q: 0=i, 1=f, 2=g, 3=o; hidx = lane*4+i)
        #pragma unroll
        for (int c = 0; c < 4; c++) {
            int ch = mych + c;
            if (clen[ch] > r) {
                float4 cv = *(float4*)&csh[ch][lane << 2];
                float cn[4], hn[4];
                float cold[4] = {cv.x, cv.y, cv.z, cv.w};
                #pragma unroll
                for (int i = 0; i < 4; i++) {
                    float ig = sigmoidf_(acc[c][0 + i]);
                    float fg = sigmoidf_(acc[c][4 + i]);
                    float gg = tanhf_(acc[c][8 + i]);
                    float og = sigmoidf_(acc[c][12 + i]);
                    cn[i] = fg * cold[i] + ig * gg;
                    hn[i] = og * tanhf_(cn[i]);
                }
                *(float4*)&csh[ch][lane << 2] = make_float4(cn[0], cn[1], cn[2], cn[3]);
                *(float4*)&ins[ch][CC + (lane << 2)] = make_float4(hn[0], hn[1], hn[2], hn[3]);
            }
        }
        // next iteration's __syncthreads (after cev stage) orders these writes vs GEMM reads
    }

    __syncthreads();
    // epilogue: scatter final h into out[b][hid][y][x]
    for (int i = tid; i < 32*HID; i += 256) {
        int ch = i >> 7, hidx = i & 127;
        if (clen[ch] > 0) {
            int rf = crf[ch];
            int y = rf >> 7, x = rf & 127;
            out[((cb[ch]*HID + hidx)*128 + y)*128 + x] = ins[ch][CC + hidx];
        }
    }
}

extern "C" void kernel_launch(void* const* d_in, const int* in_sizes, int n_in,
                              void* d_out, int out_size) {
    const float* features = (const float*)d_in[0];
    const int*   coords   = (const int*)  d_in[1];
    const float* w_ih     = (const float*)d_in[2];
    const float* w_hh     = (const float*)d_in[3];
    const float* b_ih     = (const float*)d_in[4];
    const float* b_hh     = (const float*)d_in[5];
    float* out = (float*)d_out;

    k_zero_out<<<OUT_ELEMS/4/256, 256>>>((float4*)out);
    k_zero_scratch<<<512, 256>>>();
    k_prep_w<<<(KTOT*GATES + 255)/256, 256>>>(w_ih, w_hh, b_ih, b_hh);
    k_rf_count_rank<<<BB, 1024>>>(coords);
    k_offsets<<<BB, 1024>>>();
    k_scatter<<<(BB*NN + 255)/256, 256>>>();
    k_bases<<<1, 1024>>>();
    k_chains<<<(BB*NN + 255)/256, 256>>>();
    k_lstm<<<(BB*NN + 31)/32, 256>>>(features, out);
}

// round 2
// speedup vs baseline: 1.3029x; 1.3029x over previous
#include <cuda_runtime.h>

// Problem constants (fixed by the dataset reference)
#define BB   8
#define NN   2048
#define CC   16
#define HID  128
#define RFN  16384      // 128*128 receptive fields
#define KTOT 144        // C + HID
#define GATES 512       // 4*HID
#define OUT_ELEMS (BB*HID*128*128)

// ---------------- device scratch (no allocations allowed) ----------------
__device__ int   g_rf[BB*NN];
__device__ int   g_rank[BB*NN];
__device__ int   g_count[BB*RFN];
__device__ int   g_offset[BB*RFN];
__device__ int   g_sorted[BB*NN];
__device__ int   g_hist[NN+1];
__device__ int   g_base[NN+1];
__device__ int   g_cursor[NN+1];
__device__ int   g_nactive;
__device__ int4  g_chains[BB*NN];       // {b, rf, offset, len}
__device__ float g_WT[KTOT*GATES];      // transposed [k][g]; rows 0..15 = w_ih, 16..143 = w_hh
__device__ float g_bias[GATES];

// ---------------- helpers ----------------
__device__ __forceinline__ float sigmoidf_(float x) {
    return __fdividef(1.0f, 1.0f + __expf(-x));
}
__device__ __forceinline__ float tanhf_(float x) {
    float ax = fabsf(x);
    float e  = __expf(-2.0f * ax);
    float t  = __fdividef(1.0f - e, 1.0f + e);
    return copysignf(t, x);
}

// K0: zero the 64MB output
__global__ void k_zero_out(float4* __restrict__ out) {
    int i = blockIdx.x * blockDim.x + threadIdx.x;
    if (i < OUT_ELEMS/4) out[i] = make_float4(0.f,0.f,0.f,0.f);
}

// K1: zero scratch + build transposed weights + fused bias (all independent)
__global__ void k_init(const float* __restrict__ w_ih, const float* __restrict__ w_hh,
                       const float* __restrict__ b_ih, const float* __restrict__ b_hh) {
    int i = blockIdx.x * blockDim.x + threadIdx.x;     // 131072 threads
    if (i < BB*RFN) g_count[i] = 0;
    if (i <= NN) { g_hist[i] = 0; g_cursor[i] = 0; }
    if (i == 0) g_nactive = 0;
    if (i < KTOT*GATES) {
        int k = i / GATES, g = i % GATES;
        g_WT[i] = (k < CC) ? w_ih[g*CC + k] : w_hh[g*HID + (k - CC)];
    }
    if (i < GATES) g_bias[i] = b_ih[i] + b_hh[i];
}

// K2: rf id + per-(b,rf) histogram (mostly distinct addresses -> cheap atomics)
__global__ void k_rf_count(const int* __restrict__ coords) {
    int t = blockIdx.x * blockDim.x + threadIdx.x;
    if (t >= BB*NN) return;
    int x = coords[t*2 + 0];
    int y = coords[t*2 + 1];
    int rf = y * 128 + x;
    g_rf[t] = rf;
    int b = t / NN;
    atomicAdd(&g_count[b*RFN + rf], 1);
}

// K3: stable rank. 64 blocks = (batch, 256-event chunk); full batch rf table in shared.
__global__ void __launch_bounds__(256) k_rank() {
    __shared__ int rfsh[NN];
    int b = blockIdx.x >> 3;
    int chunk = blockIdx.x & 7;
    int tid = threadIdx.x;
    for (int i = tid; i < NN; i += 256) rfsh[i] = g_rf[b*NN + i];
    __syncthreads();
    int n = chunk * 256 + tid;
    int myrf = rfsh[n];
    int r = 0;
    if (g_count[b*RFN + myrf] > 1) {      // singleton RFs (≈90%) skip the scan
        int m = 0;
        for (; m + 4 <= n; m += 4) {
            r += (rfsh[m]   == myrf);
            r += (rfsh[m+1] == myrf);
            r += (rfsh[m+2] == myrf);
            r += (rfsh[m+3] == myrf);
        }
        for (; m < n; m++) r += (rfsh[m] == myrf);
    }
    g_rank[b*NN + n] = r;
}

// K4: per-batch exclusive prefix sum of counts (1 block/batch, 1024 thr, 16 bins/thr)
__global__ void k_offsets() {
    __shared__ int ssum[1024];
    int b = blockIdx.x, tid = threadIdx.x;
    int base = b*RFN + tid*16;
    int cs[16];
    int tot = 0;
    #pragma unroll
    for (int i = 0; i < 16; i++) {
        int c = g_count[base + i];
        cs[i] = tot;
        tot += c;
    }
    ssum[tid] = tot;
    __syncthreads();
    for (int d = 1; d < 1024; d <<= 1) {
        int v = (tid >= d) ? ssum[tid - d] : 0;
        __syncthreads();
        ssum[tid] += v;
        __syncthreads();
    }
    int prev = ssum[tid] - tot;
    #pragma unroll
    for (int i = 0; i < 16; i++) g_offset[base + i] = prev + cs[i];
}

// K5: stable scatter of events into chain order + chain-length histogram
//     (warp-aggregated atomic: g_hist[1] would otherwise take ~15K serialized adds)
__global__ void k_scatter() {
    int t = blockIdx.x * blockDim.x + threadIdx.x;
    if (t >= BB*NN) return;
    int b = t / NN, n = t % NN;
    int rf = g_rf[t];
    int r  = g_rank[t];
    int off = g_offset[b*RFN + rf];
    g_sorted[b*NN + off + r] = n;
    if (r == 0) {
        int cnt = g_count[b*RFN + rf];
        unsigned act = __activemask();
        unsigned mm  = __match_any_sync(act, cnt);
        int lane = threadIdx.x & 31;
        int leader = __ffs(mm) - 1;
        if (lane == leader) atomicAdd(&g_hist[cnt], __popc(mm));
    }
}

// K6: length-descending bases + n_active via parallel suffix scan over 2048 lengths
__global__ void __launch_bounds__(1024) k_bases() {
    __shared__ int part[1024];
    int t = threadIdx.x;
    int LA = NN - 2*t;        // t=0 -> 2048, t=1023 -> 2
    int LB = LA - 1;          // t=1023 -> 1
    int hA = g_hist[LA];
    int hB = g_hist[LB];
    int tot = hA + hB;
    part[t] = tot;
    __syncthreads();
    for (int d = 1; d < 1024; d <<= 1) {
        int v = (t >= d) ? part[t - d] : 0;
        __syncthreads();
        part[t] += v;
        __syncthreads();
    }
    int excl = part[t] - tot;
    g_base[LA] = excl;
    g_base[LB] = excl + hA;
    if (t == 1023) g_nactive = part[1023];
}

// K7: register chains, grouped by length (longest first), warp-aggregated cursor atomics
__global__ void k_chains() {
    int t = blockIdx.x * blockDim.x + threadIdx.x;
    if (t >= BB*NN) return;
    if (g_rank[t] != 0) return;
    int b = t / NN;
    int rf = g_rf[t];
    int cidx = b*RFN + rf;
    int L   = g_count[cidx];
    int off = g_offset[cidx];

    unsigned act = __activemask();
    unsigned mm  = __match_any_sync(act, L);
    int lane = threadIdx.x & 31;
    int leader = __ffs(mm) - 1;
    int prefix = __popc(mm & ((1u << lane) - 1));
    int base = 0;
    if (lane == leader) base = atomicAdd(&g_cursor[L], __popc(mm));
    base = __shfl_sync(mm, base, leader);
    int pos = g_base[L] + base + prefix;
    g_chains[pos] = make_int4(b, rf, off, L);
}

// K8: main LSTM kernel — 32 chains per block, thread tile = 4 chains x 16 gates
__global__ void __launch_bounds__(256) k_lstm(const float* __restrict__ feat,
                                              float* __restrict__ out) {
    __shared__ float ins[32][KTOT];   // [chain][x(16) | h(128)]
    __shared__ float csh[32][HID];
    __shared__ float bsh[GATES];
    __shared__ int   cb[32], crf[32], coff[32], clen[32], cev[32];
    __shared__ int   smaxlen;

    int tid  = threadIdx.x;
    int lane = tid & 31;
    int warp = tid >> 5;
    int nact = g_nactive;
    int cbase = blockIdx.x * 32;
    if (cbase >= nact) return;

    if (tid < 32) {
        int bb = 0, rr = 0, oo = 0, ll = 0;
        if (cbase + tid < nact) {
            int4 m = g_chains[cbase + tid];
            bb = m.x; rr = m.y; oo = m.z; ll = m.w;
        }
        cb[tid] = bb; crf[tid] = rr; coff[tid] = oo; clen[tid] = ll;
    }
    for (int i = tid; i < GATES; i += 256) bsh[i] = g_bias[i];
    for (int i = tid; i < 32*HID; i += 256) {
        int ch = i >> 7, k = i & 127;
        csh[ch][k] = 0.f;
        ins[ch][CC + k] = 0.f;
    }
    for (int i = tid; i < 32*CC; i += 256) {
        int ch = i >> 4, c = i & 15;
        ins[ch][c] = 0.f;
    }
    __syncthreads();
    if (tid == 0) {
        int m = 0;
        for (int i = 0; i < 32; i++) m = max(m, clen[i]);
        smaxlen = m;
    }
    __syncthreads();
    int maxlen = smaxlen;
    int mych = warp << 2;

    for (int r = 0; r < maxlen; r++) {
        // stage current event index per chain
        if (tid < 32) cev[tid] = (clen[tid] > r) ? g_sorted[cb[tid]*NN + coff[tid] + r] : -1;
        __syncthreads();
        // stage x
        for (int i = tid; i < 32*CC; i += 256) {
            int ch = i >> 4, c = i & 15;
            int e = cev[ch];
            if (e >= 0) ins[ch][c] = feat[(cb[ch]*NN + e)*CC + c];
        }
        __syncthreads();

        // gates = bias + [x|h] @ W_T   (step 0: h == 0 -> only K=16 needed)
        float acc[4][16];
        #pragma unroll
        for (int q = 0; q < 4; q++) {
            float4 bv = *(const float4*)&bsh[q*128 + (lane << 2)];
            #pragma unroll
            for (int c = 0; c < 4; c++) {
                acc[c][q*4+0] = bv.x; acc[c][q*4+1] = bv.y;
                acc[c][q*4+2] = bv.z; acc[c][q*4+3] = bv.w;
            }
        }
        int kend = (r == 0) ? CC : KTOT;
        #pragma unroll 4
        for (int k = 0; k < kend; k++) {
            const float* wk = g_WT + k*GATES + (lane << 2);
            float4 w0 = *(const float4*)(wk);
            float4 w1 = *(const float4*)(wk + 128);
            float4 w2 = *(const float4*)(wk + 256);
            float4 w3 = *(const float4*)(wk + 384);
            #pragma unroll
            for (int c = 0; c < 4; c++) {
                float iv = ins[mych + c][k];
                acc[c][0]  += iv*w0.x; acc[c][1]  += iv*w0.y; acc[c][2]  += iv*w0.z; acc[c][3]  += iv*w0.w;
                acc[c][4]  += iv*w1.x; acc[c][5]  += iv*w1.y; acc[c][6]  += iv*w1.z; acc[c][7]  += iv*w1.w;
                acc[c][8]  += iv*w2.x; acc[c][9]  += iv*w2.y; acc[c][10] += iv*w2.z; acc[c][11] += iv*w2.w;
                acc[c][12] += iv*w3.x; acc[c][13] += iv*w3.y; acc[c][14] += iv*w3.z; acc[c][15] += iv*w3.w;
            }
        }
        __syncthreads();  // all reads of ins/h done before state update

        // activations + state update (q: 0=i, 1=f, 2=g, 3=o; hidx = lane*4+i)
        #pragma unroll
        for (int c = 0; c < 4; c++) {
            int ch = mych + c;
            if (clen[ch] > r) {
                float4 cv = *(float4*)&csh[ch][lane << 2];
                float cn[4], hn[4];
                float cold[4] = {cv.x, cv.y, cv.z, cv.w};
                #pragma unroll
                for (int i = 0; i < 4; i++) {
                    float ig = sigmoidf_(acc[c][0 + i]);
                    float fg = sigmoidf_(acc[c][4 + i]);
                    float gg = tanhf_(acc[c][8 + i]);
                    float og = sigmoidf_(acc[c][12 + i]);
                    cn[i] = fg * cold[i] + ig * gg;
                    hn[i] = og * tanhf_(cn[i]);
                }
                *(float4*)&csh[ch][lane << 2] = make_float4(cn[0], cn[1], cn[2], cn[3]);
                *(float4*)&ins[ch][CC + (lane << 2)] = make_float4(hn[0], hn[1], hn[2], hn[3]);
            }
        }
        // next iteration's __syncthreads (after cev stage) orders these writes vs GEMM reads
    }

    __syncthreads();
    // epilogue: scatter final h into out[b][hid][y][x]
    for (int i = tid; i < 32*HID; i += 256) {
        int ch = i >> 7, hidx = i & 127;
        if (clen[ch] > 0) {
            int rf = crf[ch];
            int y = rf >> 7, x = rf & 127;
            out[((cb[ch]*HID + hidx)*128 + y)*128 + x] = ins[ch][CC + hidx];
        }
    }
}

extern "C" void kernel_launch(void* const* d_in, const int* in_sizes, int n_in,
                              void* d_out, int out_size) {
    const float* features = (const float*)d_in[0];
    const int*   coords   = (const int*)  d_in[1];
    const float* w_ih     = (const float*)d_in[2];
    const float* w_hh     = (const float*)d_in[3];
    const float* b_ih     = (const float*)d_in[4];
    const float* b_hh     = (const float*)d_in[5];
    float* out = (float*)d_out;

    k_zero_out<<<OUT_ELEMS/4/256, 256>>>((float4*)out);
    k_init<<<512, 256>>>(w_ih, w_hh, b_ih, b_hh);
    k_rf_count<<<(BB*NN + 255)/256, 256>>>(coords);
    k_rank<<<64, 256>>>();
    k_offsets<<<BB, 1024>>>();
    k_scatter<<<(BB*NN + 255)/256, 256>>>();
    k_bases<<<1, 1024>>>();
    k_chains<<<(BB*NN + 255)/256, 256>>>();
    k_lstm<<<(BB*NN + 31)/32, 256>>>(features, out);
}

// round 3
// speedup vs baseline: 1.4109x; 1.0829x over previous
#include <cuda_runtime.h>

// Problem constants (fixed by the dataset reference)
#define BB   8
#define NN   2048
#define CC   16
#define HID  128
#define RFN  16384      // 128*128 receptive fields
#define KTOT 144        // C + HID
#define GATES 512       // 4*HID
#define OUT_ELEMS (BB*HID*128*128)

// ---------------- device scratch (no allocations allowed) ----------------
__device__ int   g_rf[BB*NN];
__device__ int   g_count[BB*RFN];
__device__ int   g_offset[BB*RFN];   // batch-relative exclusive prefix of counts
__device__ int   g_bcur[BB*RFN];     // bucket write cursor (starts at offset)
__device__ int   g_sorted[BB*NN];
__device__ int   g_hist[NN+1];
__device__ int   g_base[NN+1];
__device__ int   g_cursor[NN+1];
__device__ int   g_nactive;
__device__ int4  g_chains[BB*NN];    // {b, rf, offset, len}
__device__ float g_WT[KTOT*GATES];   // transposed [k][g]; rows 0..15 = w_ih, 16..143 = w_hh
__device__ float g_bias[GATES];

// ---------------- helpers ----------------
__device__ __forceinline__ float sigmoidf_(float x) {
    return __fdividef(1.0f, 1.0f + __expf(-x));
}
__device__ __forceinline__ float tanhf_(float x) {
    float ax = fabsf(x);
    float e  = __expf(-2.0f * ax);
    float t  = __fdividef(1.0f - e, 1.0f + e);
    return copysignf(t, x);
}

// K0: zero 64MB output + zero scratch + build transposed weights (fused boot)
// grid = OUT_ELEMS/4/256 = 16384 blocks of 256 -> exactly one float4 per thread
__global__ void k_boot(float4* __restrict__ out,
                       const float* __restrict__ w_ih, const float* __restrict__ w_hh,
                       const float* __restrict__ b_ih, const float* __restrict__ b_hh) {
    int i = blockIdx.x * blockDim.x + threadIdx.x;
    out[i] = make_float4(0.f, 0.f, 0.f, 0.f);
    if (i < BB*RFN) g_count[i] = 0;
    if (i <= NN) { g_hist[i] = 0; g_cursor[i] = 0; }
    if (i == 0) g_nactive = 0;
    if (i < KTOT*GATES) {
        int k = i / GATES, g = i % GATES;
        g_WT[i] = (k < CC) ? w_ih[g*CC + k] : w_hh[g*HID + (k - CC)];
    }
    if (i < GATES) g_bias[i] = b_ih[i] + b_hh[i];
}

// K1: rf id + per-(b,rf) histogram (mostly distinct addresses -> cheap atomics)
__global__ void k_rf_count(const int* __restrict__ coords) {
    int t = blockIdx.x * blockDim.x + threadIdx.x;
    if (t >= BB*NN) return;
    int x = coords[t*2 + 0];
    int y = coords[t*2 + 1];
    int rf = y * 128 + x;
    g_rf[t] = rf;
    int b = t / NN;
    atomicAdd(&g_count[b*RFN + rf], 1);
}

// K2: per-batch exclusive prefix sum of counts (1 block/batch) + bucket cursors
//     + chain-length histogram (shared-mem, warp-aggregated)
__global__ void __launch_bounds__(1024) k_offsets() {
    __shared__ int ssum[1024];
    __shared__ int hsh[NN+1];
    int b = blockIdx.x, tid = threadIdx.x;
    for (int i = tid; i <= NN; i += 1024) hsh[i] = 0;
    int base = b*RFN + tid*16;
    int cs[16], cv[16];
    int tot = 0;
    #pragma unroll
    for (int i = 0; i < 16; i++) {
        int c = g_count[base + i];
        cv[i] = c;
        cs[i] = tot;
        tot += c;
    }
    ssum[tid] = tot;
    __syncthreads();
    for (int d = 1; d < 1024; d <<= 1) {
        int v = (tid >= d) ? ssum[tid - d] : 0;
        __syncthreads();
        ssum[tid] += v;
        __syncthreads();
    }
    int prev = ssum[tid] - tot;
    #pragma unroll
    for (int i = 0; i < 16; i++) {
        int off = prev + cs[i];
        g_offset[base + i] = off;
        g_bcur[base + i]   = off;
    }
    // histogram of nonzero counts (warp-aggregated to tame the L=1 hot bin)
    #pragma unroll
    for (int i = 0; i < 16; i++) {
        int c = cv[i];
        unsigned act = __activemask();
        unsigned nz  = __ballot_sync(act, c > 0);
        if (c > 0) {
            unsigned mm = __match_any_sync(nz, c);
            int lane = tid & 31;
            int leader = __ffs(mm) - 1;
            if (lane == leader) atomicAdd(&hsh[c], __popc(mm));
        }
    }
    __syncthreads();
    for (int i = tid; i <= NN; i += 1024)
        if (hsh[i]) atomicAdd(&g_hist[i], hsh[i]);
}

// K3: scatter events into buckets (arbitrary intra-bucket order; fixed later)
__global__ void k_scatter(void) {
    int t = blockIdx.x * blockDim.x + threadIdx.x;
    if (t >= BB*NN) return;
    int b = t / NN, n = t % NN;
    int rf = g_rf[t];
    int pos = atomicAdd(&g_bcur[b*RFN + rf], 1);
    g_sorted[b*NN + pos] = n;
}

// K4: length-descending bases + n_active via parallel suffix scan over 2048 lengths
__global__ void __launch_bounds__(1024) k_bases() {
    __shared__ int part[1024];
    int t = threadIdx.x;
    int LA = NN - 2*t;        // t=0 -> 2048, t=1023 -> 2
    int LB = LA - 1;          // t=1023 -> 1
    int hA = g_hist[LA];
    int hB = g_hist[LB];
    int tot = hA + hB;
    part[t] = tot;
    __syncthreads();
    for (int d = 1; d < 1024; d <<= 1) {
        int v = (t >= d) ? part[t - d] : 0;
        __syncthreads();
        part[t] += v;
        __syncthreads();
    }
    int excl = part[t] - tot;
    g_base[LA] = excl;
    g_base[LB] = excl + hA;
    if (t == 1023) g_nactive = part[1023];
}

// K5: register chains grouped by length (warp-aggregated cursor atomics)
//     + restore time order inside non-singleton buckets (insertion sort, <=~8 elems)
__global__ void k_chains() {
    int t = blockIdx.x * blockDim.x + threadIdx.x;
    if (t >= BB*RFN) return;
    int L = g_count[t];
    unsigned act = __activemask();
    unsigned nz  = __ballot_sync(act, L > 0);
    if (L == 0) return;
    int b  = t / RFN;
    int rf = t % RFN;
    int off = g_offset[t];

    unsigned mm  = __match_any_sync(nz, L);
    int lane = threadIdx.x & 31;
    int leader = __ffs(mm) - 1;
    int prefix = __popc(mm & ((1u << lane) - 1));
    int cbase = 0;
    if (lane == leader) cbase = atomicAdd(&g_cursor[L], __popc(mm));
    cbase = __shfl_sync(mm, cbase, leader);
    g_chains[g_base[L] + cbase + prefix] = make_int4(b, rf, off, L);

    if (L > 1) {
        int* s = g_sorted + b*NN + off;
        for (int i = 1; i < L; i++) {
            int v = s[i];
            int j = i - 1;
            while (j >= 0 && s[j] > v) { s[j+1] = s[j]; j--; }
            s[j+1] = v;
        }
    }
}

// K6: main LSTM kernel — 32 chains per block, thread tile = 4 chains x 16 gates
__global__ void __launch_bounds__(256) k_lstm(const float* __restrict__ feat,
                                              float* __restrict__ out) {
    __shared__ float ins[32][KTOT];   // [chain][x(16) | h(128)]
    __shared__ float csh[32][HID];
    __shared__ float bsh[GATES];
    __shared__ int   cb[32], crf[32], coff[32], clen[32], cev[32];
    __shared__ int   smaxlen;

    int tid  = threadIdx.x;
    int lane = tid & 31;
    int warp = tid >> 5;
    int nact = g_nactive;
    int cbase = blockIdx.x * 32;
    if (cbase >= nact) return;

    if (tid < 32) {
        int bb = 0, rr = 0, oo = 0, ll = 0;
        if (cbase + tid < nact) {
            int4 m = g_chains[cbase + tid];
            bb = m.x; rr = m.y; oo = m.z; ll = m.w;
        }
        cb[tid] = bb; crf[tid] = rr; coff[tid] = oo; clen[tid] = ll;
    }
    for (int i = tid; i < GATES; i += 256) bsh[i] = g_bias[i];
    for (int i = tid; i < 32*HID; i += 256) {
        int ch = i >> 7, k = i & 127;
        csh[ch][k] = 0.f;
        ins[ch][CC + k] = 0.f;
    }
    for (int i = tid; i < 32*CC; i += 256) {
        int ch = i >> 4, c = i & 15;
        ins[ch][c] = 0.f;
    }
    __syncthreads();
    if (tid == 0) {
        int m = 0;
        for (int i = 0; i < 32; i++) m = max(m, clen[i]);
        smaxlen = m;
    }
    __syncthreads();
    int maxlen = smaxlen;
    int mych = warp << 2;

    for (int r = 0; r < maxlen; r++) {
        // stage current event index per chain
        if (tid < 32) cev[tid] = (clen[tid] > r) ? g_sorted[cb[tid]*NN + coff[tid] + r] : -1;
        __syncthreads();
        // stage x
        for (int i = tid; i < 32*CC; i += 256) {
            int ch = i >> 4, c = i & 15;
            int e = cev[ch];
            if (e >= 0) ins[ch][c] = feat[(cb[ch]*NN + e)*CC + c];
        }
        __syncthreads();

        // gates = bias + [x|h] @ W_T   (step 0: h == 0 -> only K=16 needed)
        float acc[4][16];
        #pragma unroll
        for (int q = 0; q < 4; q++) {
            float4 bv = *(const float4*)&bsh[q*128 + (lane << 2)];
            #pragma unroll
            for (int c = 0; c < 4; c++) {
                acc[c][q*4+0] = bv.x; acc[c][q*4+1] = bv.y;
                acc[c][q*4+2] = bv.z; acc[c][q*4+3] = bv.w;
            }
        }
        int kend = (r == 0) ? CC : KTOT;
        #pragma unroll 4
        for (int k = 0; k < kend; k++) {
            const float* wk = g_WT + k*GATES + (lane << 2);
            float4 w0 = *(const float4*)(wk);
            float4 w1 = *(const float4*)(wk + 128);
            float4 w2 = *(const float4*)(wk + 256);
            float4 w3 = *(const float4*)(wk + 384);
            #pragma unroll
            for (int c = 0; c < 4; c++) {
                float iv = ins[mych + c][k];
                acc[c][0]  += iv*w0.x; acc[c][1]  += iv*w0.y; acc[c][2]  += iv*w0.z; acc[c][3]  += iv*w0.w;
                acc[c][4]  += iv*w1.x; acc[c][5]  += iv*w1.y; acc[c][6]  += iv*w1.z; acc[c][7]  += iv*w1.w;
                acc[c][8]  += iv*w2.x; acc[c][9]  += iv*w2.y; acc[c][10] += iv*w2.z; acc[c][11] += iv*w2.w;
                acc[c][12] += iv*w3.x; acc[c][13] += iv*w3.y; acc[c][14] += iv*w3.z; acc[c][15] += iv*w3.w;
            }
        }
        __syncthreads();  // all reads of ins/h done before state update

        // activations + state update (q: 0=i, 1=f, 2=g, 3=o; hidx = lane*4+i)
        #pragma unroll
        for (int c = 0; c < 4; c++) {
            int ch = mych + c;
            if (clen[ch] > r) {
                float4 cv = *(float4*)&csh[ch][lane << 2];
                float cn[4], hn[4];
                float cold[4] = {cv.x, cv.y, cv.z, cv.w};
                #pragma unroll
                for (int i = 0; i < 4; i++) {
                    float ig = sigmoidf_(acc[c][0 + i]);
                    float fg = sigmoidf_(acc[c][4 + i]);
                    float gg = tanhf_(acc[c][8 + i]);
                    float og = sigmoidf_(acc[c][12 + i]);
                    cn[i] = fg * cold[i] + ig * gg;
                    hn[i] = og * tanhf_(cn[i]);
                }
                *(float4*)&csh[ch][lane << 2] = make_float4(cn[0], cn[1], cn[2], cn[3]);
                *(float4*)&ins[ch][CC + (lane << 2)] = make_float4(hn[0], hn[1], hn[2], hn[3]);
            }
        }
        // next iteration's __syncthreads (after cev stage) orders these writes vs GEMM reads
    }

    __syncthreads();
    // epilogue: scatter final h into out[b][hid][y][x]
    for (int i = tid; i < 32*HID; i += 256) {
        int ch = i >> 7, hidx = i & 127;
        if (clen[ch] > 0) {
            int rf = crf[ch];
            int y = rf >> 7, x = rf & 127;
            out[((cb[ch]*HID + hidx)*128 + y)*128 + x] = ins[ch][CC + hidx];
        }
    }
}

extern "C" void kernel_launch(void* const* d_in, const int* in_sizes, int n_in,
                              void* d_out, int out_size) {
    const float* features = (const float*)d_in[0];
    const int*   coords   = (const int*)  d_in[1];
    const float* w_ih     = (const float*)d_in[2];
    const float* w_hh     = (const float*)d_in[3];
    const float* b_ih     = (const float*)d_in[4];
    const float* b_hh     = (const float*)d_in[5];
    float* out = (float*)d_out;

    k_boot<<<OUT_ELEMS/4/256, 256>>>((float4*)out, w_ih, w_hh, b_ih, b_hh);
    k_rf_count<<<(BB*NN + 255)/256, 256>>>(coords);
    k_offsets<<<BB, 1024>>>();
    k_scatter<<<(BB*NN + 255)/256, 256>>>();
    k_bases<<<1, 1024>>>();
    k_chains<<<(BB*RFN + 255)/256, 256>>>();
    k_lstm<<<(BB*NN + 31)/32, 256>>>(features, out);
}

// round 4
// speedup vs baseline: 1.5789x; 1.1191x over previous
#include <cuda_runtime.h>

// Problem constants (fixed by the dataset reference)
#define BB   8
#define NN   2048
#define CC   16
#define HID  128
#define RFN  16384      // 128*128 receptive fields
#define KTOT 144        // C + HID
#define GATES 512       // 4*HID
#define OUT_ELEMS (BB*HID*128*128)

// ---------------- device scratch (no allocations allowed) ----------------
__device__ int   g_sorted[BB*NN];    // per batch: event ids sorted by (rf, time)
__device__ int2  g_chains[BB*NN];    // {rf | off<<14, len}
__device__ int   g_nact[BB];
__device__ float g_WT[KTOT*GATES];   // transposed [k][g]; rows 0..15 = w_ih, 16..143 = w_hh
__device__ float g_bias[GATES];

// ---------------- helpers ----------------
__device__ __forceinline__ float sigmoidf_(float x) {
    return __fdividef(1.0f, 1.0f + __expf(-x));
}
__device__ __forceinline__ float tanhf_(float x) {
    float ax = fabsf(x);
    float e  = __expf(-2.0f * ax);
    float t  = __fdividef(1.0f - e, 1.0f + e);
    return copysignf(t, x);
}

// K0: zero 64MB output (grid-stride) + transposed weights + fused bias
__global__ void k_boot(float4* __restrict__ out,
                       const float* __restrict__ w_ih, const float* __restrict__ w_hh,
                       const float* __restrict__ b_ih, const float* __restrict__ b_hh) {
    int i = blockIdx.x * blockDim.x + threadIdx.x;
    int stride = gridDim.x * blockDim.x;
    const float4 z = make_float4(0.f, 0.f, 0.f, 0.f);
    for (int t = i; t < OUT_ELEMS/4; t += stride) out[t] = z;
    if (i < KTOT*GATES) {
        int k = i / GATES, g = i % GATES;
        g_WT[i] = (k < CC) ? w_ih[g*CC + k] : w_hh[g*HID + (k - CC)];
    }
    if (i < GATES) g_bias[i] = b_ih[i] + b_hh[i];
}

// K1: per-batch plan. Bitonic sort of keys (rf<<11 | n) groups events by RF in
// time order; boundary detection yields chains. One block per batch.
__global__ void __launch_bounds__(1024) k_plan(const int* __restrict__ coords) {
    __shared__ int key[NN];
    __shared__ int chcnt;
    int b = blockIdx.x, tid = threadIdx.x;
    if (tid == 0) chcnt = 0;
    for (int n = tid; n < NN; n += 1024) {
        int x = coords[(b*NN + n)*2 + 0];
        int y = coords[(b*NN + n)*2 + 1];
        key[n] = ((y*128 + x) << 11) | n;
    }
    __syncthreads();
    // bitonic sort, ascending (2048 elems, 1024 threads)
    for (int ksz = 2; ksz <= NN; ksz <<= 1) {
        for (int j = ksz >> 1; j > 0; j >>= 1) {
            #pragma unroll
            for (int base = 0; base < NN; base += 1024) {
                int i = base + tid;
                int ixj = i ^ j;
                if (ixj > i) {
                    int a = key[i], c2 = key[ixj];
                    bool asc = ((i & ksz) == 0);
                    if ((a > c2) == asc) { key[i] = c2; key[ixj] = a; }
                }
            }
            __syncthreads();
        }
    }
    // dump sorted event ids + register chains at rf boundaries
    for (int i = tid; i < NN; i += 1024) {
        int kv = key[i];
        g_sorted[b*NN + i] = kv & 2047;
        int myrf = kv >> 11;
        int prevrf = (i == 0) ? -1 : (key[i-1] >> 11);
        bool isb = (myrf != prevrf);
        unsigned bal = __ballot_sync(0xffffffffu, isb);
        if (isb) {
            int lane = tid & 31;
            int leader = __ffs(bal) - 1;
            int base2 = 0;
            if (lane == leader) base2 = atomicAdd(&chcnt, __popc(bal));
            base2 = __shfl_sync(bal, base2, leader);
            int pos = base2 + __popc(bal & ((1u << lane) - 1));
            int L = 1;
            while (i + L < NN && (key[i+L] >> 11) == myrf) L++;
            g_chains[b*NN + pos] = make_int2(myrf | (i << 14), L);
        }
    }
    __syncthreads();
    if (tid == 0) g_nact[b] = chcnt;
}

// K2: warp-autonomous LSTM. Warp = 4 chains; c-state in regs, h/x in a private
// shared slice; no block barriers. Thread tile = 4 chains x 16 gates
// (gate g = q*128 + lane*4 + i; q selects i/f/g/o).
__global__ void __launch_bounds__(256) k_lstm(const float* __restrict__ feat,
                                              float* __restrict__ out) {
    __shared__ float xsh[8][4][CC];    // per-warp x staging
    __shared__ float hsh[8][4][HID];   // per-warp h state
    int tid = threadIdx.x, lane = tid & 31, warp = tid >> 5;
    int b = blockIdx.x >> 6;                         // 64 blocks per batch
    int cbase = ((blockIdx.x & 63) << 5) + (warp << 2);
    int nact = g_nact[b];
    if (cbase >= nact) return;                        // warp-uniform

    int rf[4], off[4], len[4];
    #pragma unroll
    for (int c = 0; c < 4; c++) {
        int ci = cbase + c;
        int2 m = (ci < nact) ? g_chains[b*NN + ci] : make_int2(0, 0);
        rf[c]  = m.x & 16383;
        off[c] = m.x >> 14;
        len[c] = m.y;
    }
    int wmax = max(max(len[0], len[1]), max(len[2], len[3]));

    float bia[16];
    #pragma unroll
    for (int q = 0; q < 4; q++) {
        float4 v = *(const float4*)&g_bias[q*128 + (lane << 2)];
        bia[q*4+0] = v.x; bia[q*4+1] = v.y; bia[q*4+2] = v.z; bia[q*4+3] = v.w;
    }

    float cst[4][4];
    #pragma unroll
    for (int c = 0; c < 4; c++)
        #pragma unroll
        for (int i = 0; i < 4; i++) cst[c][i] = 0.f;

    for (int r = 0; r < wmax; r++) {
        // stage x of event r per active chain (lanes 0..3 fetch event ids)
        int e = (lane < 4 && len[lane] > r) ? g_sorted[b*NN + off[lane] + r] : -1;
        #pragma unroll
        for (int s2 = 0; s2 < 2; s2++) {
            int slot = lane + (s2 << 5);       // 0..63 -> (c, k)
            int c = slot >> 4, k = slot & 15;
            int ec = __shfl_sync(0xffffffffu, e, c);
            if (ec >= 0) xsh[warp][c][k] = feat[(b*NN + ec)*CC + k];
        }
        __syncwarp();

        float acc[4][16];
        #pragma unroll
        for (int c = 0; c < 4; c++)
            #pragma unroll
            for (int g = 0; g < 16; g++) acc[c][g] = bia[g];

        // K part 1: x contribution (K=16) — the only part for first-step chains
        #pragma unroll 4
        for (int k = 0; k < CC; k++) {
            const float* wk = g_WT + k*GATES + (lane << 2);
            float4 w0 = *(const float4*)(wk);
            float4 w1 = *(const float4*)(wk + 128);
            float4 w2 = *(const float4*)(wk + 256);
            float4 w3 = *(const float4*)(wk + 384);
            #pragma unroll
            for (int c = 0; c < 4; c++) {
                float iv = xsh[warp][c][k];
                acc[c][0]  += iv*w0.x; acc[c][1]  += iv*w0.y; acc[c][2]  += iv*w0.z; acc[c][3]  += iv*w0.w;
                acc[c][4]  += iv*w1.x; acc[c][5]  += iv*w1.y; acc[c][6]  += iv*w1.z; acc[c][7]  += iv*w1.w;
                acc[c][8]  += iv*w2.x; acc[c][9]  += iv*w2.y; acc[c][10] += iv*w2.z; acc[c][11] += iv*w2.w;
                acc[c][12] += iv*w3.x; acc[c][13] += iv*w3.y; acc[c][14] += iv*w3.z; acc[c][15] += iv*w3.w;
            }
        }
        // K part 2: h contribution (K=128), only after the first step
        if (r > 0) {
            #pragma unroll 4
            for (int k = 0; k < HID; k++) {
                const float* wk = g_WT + (CC + k)*GATES + (lane << 2);
                float4 w0 = *(const float4*)(wk);
                float4 w1 = *(const float4*)(wk + 128);
                float4 w2 = *(const float4*)(wk + 256);
                float4 w3 = *(const float4*)(wk + 384);
                #pragma unroll
                for (int c = 0; c < 4; c++) {
                    float iv = hsh[warp][c][k];
                    acc[c][0]  += iv*w0.x; acc[c][1]  += iv*w0.y; acc[c][2]  += iv*w0.z; acc[c][3]  += iv*w0.w;
                    acc[c][4]  += iv*w1.x; acc[c][5]  += iv*w1.y; acc[c][6]  += iv*w1.z; acc[c][7]  += iv*w1.w;
                    acc[c][8]  += iv*w2.x; acc[c][9]  += iv*w2.y; acc[c][10] += iv*w2.z; acc[c][11] += iv*w2.w;
                    acc[c][12] += iv*w3.x; acc[c][13] += iv*w3.y; acc[c][14] += iv*w3.z; acc[c][15] += iv*w3.w;
                }
            }
        }
        __syncwarp();   // all hsh reads complete before overwrite

        #pragma unroll
        for (int c = 0; c < 4; c++) {
            if (len[c] > r) {
                float hn[4];
                #pragma unroll
                for (int i = 0; i < 4; i++) {
                    float ig = sigmoidf_(acc[c][0 + i]);
                    float fg = sigmoidf_(acc[c][4 + i]);
                    float gg = tanhf_(acc[c][8 + i]);
                    float og = sigmoidf_(acc[c][12 + i]);
                    cst[c][i] = fg * cst[c][i] + ig * gg;
                    hn[i] = og * tanhf_(cst[c][i]);
                }
                if (len[c] == r + 1) {
                    // chain finished: stream h straight to out[b][hid][y][x]
                    int y = rf[c] >> 7, x = rf[c] & 127;
                    #pragma unroll
                    for (int i = 0; i < 4; i++)
                        out[((b*HID + (lane << 2) + i)*128 + y)*128 + x] = hn[i];
                } else {
                    *(float4*)&hsh[warp][c][lane << 2] = make_float4(hn[0], hn[1], hn[2], hn[3]);
                }
            }
        }
        __syncwarp();
    }
}

extern "C" void kernel_launch(void* const* d_in, const int* in_sizes, int n_in,
                              void* d_out, int out_size) {
    const float* features = (const float*)d_in[0];
    const int*   coords   = (const int*)  d_in[1];
    const float* w_ih     = (const float*)d_in[2];
    const float* w_hh     = (const float*)d_in[3];
    const float* b_ih     = (const float*)d_in[4];
    const float* b_hh     = (const float*)d_in[5];
    float* out = (float*)d_out;

    k_boot<<<2048, 256>>>((float4*)out, w_ih, w_hh, b_ih, b_hh);
    k_plan<<<BB, 1024>>>(coords);
    k_lstm<<<512, 256>>>(features, out);
}

// round 5
// speedup vs baseline: 2.5593x; 1.6209x over previous
#include <cuda_runtime.h>

// Problem constants (fixed by the dataset reference)
#define BB   8
#define NN   2048
#define CC   16
#define HID  128
#define RFN  16384      // 128*128 receptive fields
#define KTOT 144        // C + HID
#define GATES 512       // 4*HID
#define K4   (KTOT/4)   // 36 float4 groups along K
#define OUT_ELEMS (BB*HID*128*128)

// ---------------- device scratch (no allocations allowed) ----------------
__device__ int    g_sorted[BB*NN];     // per batch: event ids sorted by (rf, time)
__device__ int    g_single[BB*NN];     // ev | b<<11 | rf<<14
__device__ int2   g_mult[BB*NN];       // {rf | b<<14 | off<<17, len}
__device__ int    g_ns, g_nm;
__device__ float  g_WT[CC*GATES];      // x-part weights, [k][gate] (singles)
__device__ float4 g_W4[K4*4*HID];      // [(k4*4+q)*128 + h] = W[q*128+h][4k4..4k4+3]
__device__ float  g_bias[GATES];

// ---------------- helpers ----------------
__device__ __forceinline__ float sigmoidf_(float x) {
    return __fdividef(1.0f, 1.0f + __expf(-x));
}
__device__ __forceinline__ float tanhf_(float x) {
    float ax = fabsf(x);
    float e  = __expf(-2.0f * ax);
    float t  = __fdividef(1.0f - e, 1.0f + e);
    return copysignf(t, x);
}

// K0: zero 64MB output + build weight layouts + fused bias + counters
__global__ void k_boot(float4* __restrict__ out,
                       const float* __restrict__ w_ih, const float* __restrict__ w_hh,
                       const float* __restrict__ b_ih, const float* __restrict__ b_hh) {
    int i = blockIdx.x * blockDim.x + threadIdx.x;
    int stride = gridDim.x * blockDim.x;
    const float4 z = make_float4(0.f, 0.f, 0.f, 0.f);
    for (int t = i; t < OUT_ELEMS/4; t += stride) out[t] = z;
    if (i < CC*GATES) {                        // x-part transposed [k][g]
        int k = i / GATES, g = i % GATES;
        g_WT[i] = w_ih[g*CC + k];
    }
    if (i < K4*4*HID) {                        // multi layout
        int k4 = i / (4*HID);
        int rem = i % (4*HID);
        int q = rem / HID, h = rem % HID;
        int g = q*HID + h;
        float v[4];
        #pragma unroll
        for (int j = 0; j < 4; j++) {
            int k = k4*4 + j;
            v[j] = (k < CC) ? w_ih[g*CC + k] : w_hh[g*HID + (k - CC)];
        }
        g_W4[i] = make_float4(v[0], v[1], v[2], v[3]);
    }
    if (i < GATES) g_bias[i] = b_ih[i] + b_hh[i];
    if (i == 0) { g_ns = 0; g_nm = 0; }
}

// K1: per-batch plan via in-shared counting sort (u16-packed counters).
__global__ void __launch_bounds__(1024) k_plan(const int* __restrict__ coords) {
    __shared__ unsigned int pcnt[RFN/2];     // two u16 counters per int (32KB)
    __shared__ unsigned short srf[NN];
    __shared__ unsigned short sev[NN];
    __shared__ int sscan[1024];
    int b = blockIdx.x, tid = threadIdx.x;

    #pragma unroll
    for (int j = 0; j < 8; j++) pcnt[tid + j*1024] = 0;
    __syncthreads();

    // count (keep this thread's rf ids in regs for the scatter pass)
    int n0 = tid, n1 = tid + 1024;
    int x0 = coords[(b*NN + n0)*2], y0 = coords[(b*NN + n0)*2 + 1];
    int x1 = coords[(b*NN + n1)*2], y1 = coords[(b*NN + n1)*2 + 1];
    int rf0 = y0*128 + x0, rf1 = y1*128 + x1;
    atomicAdd(&pcnt[rf0 >> 1], 1u << ((rf0 & 1)*16));
    atomicAdd(&pcnt[rf1 >> 1], 1u << ((rf1 & 1)*16));
    __syncthreads();

    // exclusive scan over 16384 u16 counts (16 per thread, packed in 8 ints)
    unsigned int ex[8];
    int run = 0;
    #pragma unroll
    for (int j = 0; j < 8; j++) {
        unsigned int v = pcnt[tid*8 + j];
        int c0 = v & 0xFFFF, c1 = v >> 16;
        int e0 = run; run += c0;
        int e1 = run; run += c1;
        ex[j] = (unsigned)e0 | ((unsigned)e1 << 16);
    }
    sscan[tid] = run;
    __syncthreads();
    for (int d = 1; d < 1024; d <<= 1) {
        int v = (tid >= d) ? sscan[tid - d] : 0;
        __syncthreads();
        sscan[tid] += v;
        __syncthreads();
    }
    unsigned int prev = (unsigned)(sscan[tid] - run);
    unsigned int prevp = prev * 0x00010001u;
    #pragma unroll
    for (int j = 0; j < 8; j++) pcnt[tid*8 + j] = ex[j] + prevp;
    __syncthreads();

    // scatter (pcnt now serves as cursors)
    {
        unsigned int p = atomicAdd(&pcnt[rf0 >> 1], 1u << ((rf0 & 1)*16));
        int pos = (p >> ((rf0 & 1)*16)) & 0xFFFF;
        sev[pos] = (unsigned short)n0; srf[pos] = (unsigned short)rf0;
        p = atomicAdd(&pcnt[rf1 >> 1], 1u << ((rf1 & 1)*16));
        pos = (p >> ((rf1 & 1)*16)) & 0xFFFF;
        sev[pos] = (unsigned short)n1; srf[pos] = (unsigned short)rf1;
    }
    __syncthreads();

    // pass A: restore time order inside each bucket (tiny insertion sorts)
    #pragma unroll
    for (int s = 0; s < 2; s++) {
        int i = tid + s*1024;
        int rf = srf[i];
        int pv = (i == 0) ? -1 : (int)srf[i-1];
        if (rf != pv) {
            int L = 1;
            while (i + L < NN && srf[i+L] == rf) L++;
            if (L > 1) {
                for (int a = 1; a < L; a++) {
                    unsigned short v = sev[i+a];
                    int j = a - 1;
                    while (j >= 0 && sev[i+j] > v) { sev[i+j+1] = sev[i+j]; j--; }
                    sev[i+j+1] = v;
                }
            }
        }
    }
    __syncthreads();

    // pass B: emit chain records + dump sorted event ids
    #pragma unroll
    for (int s = 0; s < 2; s++) {
        int i = tid + s*1024;
        g_sorted[b*NN + i] = sev[i];
        int rf = srf[i];
        int pv = (i == 0) ? -1 : (int)srf[i-1];
        bool isb = (rf != pv);
        int L = 0;
        if (isb) {
            L = 1;
            while (i + L < NN && srf[i+L] == rf) L++;
        }
        bool sgl = isb && (L == 1);
        unsigned bal = __ballot_sync(0xffffffffu, sgl);
        if (sgl) {
            int lane = tid & 31;
            int leader = __ffs(bal) - 1;
            int base = 0;
            if (lane == leader) base = atomicAdd(&g_ns, __popc(bal));
            base = __shfl_sync(bal, base, leader);
            g_single[base + __popc(bal & ((1u << lane) - 1))] =
                (int)sev[i] | (b << 11) | (rf << 14);
        } else if (isb) {
            int idx = atomicAdd(&g_nm, 1);
            g_mult[idx] = make_int2(rf | (b << 14) | (i << 17), L);
        }
    }
}

// K2: singleton chains (h=c=0): gates = bias + x @ Wx^T, W_x staged in shared.
// Warp = 4 chains, lane = 16 gates (gate q*128 + lane*4 + i).
__global__ void __launch_bounds__(256) k_single(const float* __restrict__ feat,
                                                float* __restrict__ out) {
    __shared__ float Ws[CC*GATES];    // 32KB
    __shared__ float bs[GATES];
    __shared__ float xsh[8][4][CC];
    int tid = threadIdx.x, lane = tid & 31, warp = tid >> 5;
    int ns = g_ns;

    for (int i = tid; i < CC*GATES; i += 256) Ws[i] = g_WT[i];
    for (int i = tid; i < GATES; i += 256) bs[i] = g_bias[i];
    __syncthreads();

    int idx0 = blockIdx.x * 32 + (warp << 2);
    if (idx0 >= ns) return;

    int rec = -1;
    if (lane < 4 && idx0 + lane < ns) rec = g_single[idx0 + lane];

    // stage x for up to 4 chains
    #pragma unroll
    for (int s2 = 0; s2 < 2; s2++) {
        int slot = lane + (s2 << 5);
        int c = slot >> 4, k = slot & 15;
        int rc = __shfl_sync(0xffffffffu, rec, c);
        if (rc >= 0) {
            int ev = rc & 2047, bb = (rc >> 11) & 7;
            xsh[warp][c][k] = feat[(bb*NN + ev)*CC + k];
        }
    }
    __syncwarp();

    float acc[4][16];
    #pragma unroll
    for (int q = 0; q < 4; q++) {
        float4 bv = *(const float4*)&bs[q*128 + (lane << 2)];
        #pragma unroll
        for (int c = 0; c < 4; c++) {
            acc[c][q*4+0] = bv.x; acc[c][q*4+1] = bv.y;
            acc[c][q*4+2] = bv.z; acc[c][q*4+3] = bv.w;
        }
    }
    #pragma unroll
    for (int k = 0; k < CC; k++) {
        const float* wk = Ws + k*GATES + (lane << 2);
        float4 w0 = *(const float4*)(wk);
        float4 w1 = *(const float4*)(wk + 128);
        float4 w2 = *(const float4*)(wk + 256);
        float4 w3 = *(const float4*)(wk + 384);
        #pragma unroll
        for (int c = 0; c < 4; c++) {
            float iv = xsh[warp][c][k];
            acc[c][0]  += iv*w0.x; acc[c][1]  += iv*w0.y; acc[c][2]  += iv*w0.z; acc[c][3]  += iv*w0.w;
            acc[c][4]  += iv*w1.x; acc[c][5]  += iv*w1.y; acc[c][6]  += iv*w1.z; acc[c][7]  += iv*w1.w;
            acc[c][8]  += iv*w2.x; acc[c][9]  += iv*w2.y; acc[c][10] += iv*w2.z; acc[c][11] += iv*w2.w;
            acc[c][12] += iv*w3.x; acc[c][13] += iv*w3.y; acc[c][14] += iv*w3.z; acc[c][15] += iv*w3.w;
        }
    }
    #pragma unroll
    for (int c = 0; c < 4; c++) {
        int rc = __shfl_sync(0xffffffffu, rec, c);
        if (rc >= 0) {
            int bb = (rc >> 11) & 7, rf = rc >> 14;
            int y = rf >> 7, x = rf & 127;
            #pragma unroll
            for (int i = 0; i < 4; i++) {
                float cn = sigmoidf_(acc[c][0 + i]) * tanhf_(acc[c][8 + i]);  // c_prev=0, f-gate dead
                float hh = sigmoidf_(acc[c][12 + i]) * tanhf_(cn);
                out[((bb*HID + (lane << 2) + i)*128 + y)*128 + x] = hh;
            }
        }
    }
}

// K3: multi-event chains. Block = 128 threads = hidden units; 2 chains/block.
// Thread h owns gates {h, 128+h, 256+h, 384+h} = i,f,g,o of hid h -> c in regs.
__global__ void __launch_bounds__(128) k_multi(const float* __restrict__ feat,
                                               float* __restrict__ out) {
    __shared__ __align__(16) float ivec[2][KTOT];   // [chain][x(16) | h(128)]
    int h = threadIdx.x;
    int nm = g_nm;

    float b0 = g_bias[h], b1 = g_bias[128 + h], b2 = g_bias[256 + h], b3 = g_bias[384 + h];

    for (int pair = blockIdx.x; 2*pair < nm; pair += gridDim.x) {
        int2 m0 = g_mult[2*pair];
        int2 m1 = (2*pair + 1 < nm) ? g_mult[2*pair + 1] : make_int2(0, 0);
        int rfA = m0.x & 0x3FFF, bA = (m0.x >> 14) & 7, offA = m0.x >> 17, lenA = m0.y;
        int rfB = m1.x & 0x3FFF, bB = (m1.x >> 14) & 7, offB = m1.x >> 17, lenB = m1.y;
        int maxlen = max(lenA, lenB);

        float cstA = 0.f, cstB = 0.f;

        for (int r = 0; r < maxlen; r++) {
            // stage x (threads 0..15 -> chain A, 16..31 -> chain B)
            if (h < 16) {
                if (lenA > r) {
                    int e = g_sorted[bA*NN + offA + r];
                    ivec[0][h] = feat[(bA*NN + e)*CC + h];
                }
            } else if (h < 32) {
                if (lenB > r) {
                    int e = g_sorted[bB*NN + offB + r];
                    ivec[1][h - 16] = feat[(bB*NN + e)*CC + (h - 16)];
                }
            }
            __syncthreads();

            float a0 = b0, a1 = b1, a2 = b2, a3 = b3;   // chain A gates i,f,g,o
            float c0 = b0, c1 = b1, c2 = b2, c3 = b3;   // chain B
            int k4max = (r == 0) ? (CC/4) : K4;
            #pragma unroll 4
            for (int k4 = 0; k4 < k4max; k4++) {
                float4 iA = *(const float4*)&ivec[0][k4*4];
                float4 iB = *(const float4*)&ivec[1][k4*4];
                int base = (k4 << 2)*HID + h;
                float4 w0 = g_W4[base];
                float4 w1 = g_W4[base + HID];
                float4 w2 = g_W4[base + 2*HID];
                float4 w3 = g_W4[base + 3*HID];
                a0 += iA.x*w0.x + iA.y*w0.y + iA.z*w0.z + iA.w*w0.w;
                a1 += iA.x*w1.x + iA.y*w1.y + iA.z*w1.z + iA.w*w1.w;
                a2 += iA.x*w2.x + iA.y*w2.y + iA.z*w2.z + iA.w*w2.w;
                a3 += iA.x*w3.x + iA.y*w3.y + iA.z*w3.z + iA.w*w3.w;
                c0 += iB.x*w0.x + iB.y*w0.y + iB.z*w0.z + iB.w*w0.w;
                c1 += iB.x*w1.x + iB.y*w1.y + iB.z*w1.z + iB.w*w1.w;
                c2 += iB.x*w2.x + iB.y*w2.y + iB.z*w2.z + iB.w*w2.w;
                c3 += iB.x*w3.x + iB.y*w3.y + iB.z*w3.z + iB.w*w3.w;
            }
            __syncthreads();   // all ivec reads done before h overwrite

            if (lenA > r) {
                float ig = sigmoidf_(a0), fg = sigmoidf_(a1);
                float gg = tanhf_(a2),   og = sigmoidf_(a3);
                cstA = fg*cstA + ig*gg;
                float hn = og * tanhf_(cstA);
                if (r == lenA - 1) {
                    int y = rfA >> 7, x = rfA & 127;
                    out[((bA*HID + h)*128 + y)*128 + x] = hn;
                } else {
                    ivec[0][CC + h] = hn;
                }
            }
            if (lenB > r) {
                float ig = sigmoidf_(c0), fg = sigmoidf_(c1);
                float gg = tanhf_(c2),   og = sigmoidf_(c3);
                cstB = fg*cstB + ig*gg;
                float hn = og * tanhf_(cstB);
                if (r == lenB - 1) {
                    int y = rfB >> 7, x = rfB & 127;
                    out[((bB*HID + h)*128 + y)*128 + x] = hn;
                } else {
                    ivec[1][CC + h] = hn;
                }
            }
            __syncthreads();
        }
    }
}

extern "C" void kernel_launch(void* const* d_in, const int* in_sizes, int n_in,
                              void* d_out, int out_size) {
    const float* features = (const float*)d_in[0];
    const int*   coords   = (const int*)  d_in[1];
    const float* w_ih     = (const float*)d_in[2];
    const float* w_hh     = (const float*)d_in[3];
    const float* b_ih     = (const float*)d_in[4];
    const float* b_hh     = (const float*)d_in[5];
    float* out = (float*)d_out;

    k_boot<<<4096, 256>>>((float4*)out, w_ih, w_hh, b_ih, b_hh);
    k_plan<<<BB, 1024>>>(coords);
    k_single<<<512, 256>>>(features, out);
    k_multi<<<1024, 128>>>(features, out);
}

// round 6
// speedup vs baseline: 2.8918x; 1.1299x over previous
#include <cuda_runtime.h>

// Problem constants (fixed by the dataset reference)
#define BB   8
#define NN   2048
#define CC   16
#define HID  128
#define RFN  16384      // 128*128 receptive fields
#define KTOT 144        // C + HID
#define GATES 512       // 4*HID
#define K4   (KTOT/4)   // 36 float4 groups along K
#define OUT_ELEMS (BB*HID*128*128)

#define MUL_BLOCKS 512
#define SGL_BLOCKS 256
#define LSTM_GRID  (MUL_BLOCKS + SGL_BLOCKS)

// ---------------- device scratch (no allocations allowed) ----------------
__device__ int    g_sorted[BB*NN];     // per batch: event ids sorted by (rf, time)
__device__ int    g_single[BB*NN];     // ev | b<<11 | rf<<14
__device__ int2   g_mult[BB*NN];       // {rf | b<<14 | off<<17, len}
__device__ int    g_ns, g_nm;
__device__ float  g_WT[CC*GATES];      // x-part weights, [k][gate] (singles)
__device__ float4 g_W4[K4*4*HID];      // [(k4*4+q)*128 + h] = W[q*128+h][4k4..4k4+3]
__device__ float  g_bias[GATES];

// ---------------- helpers ----------------
__device__ __forceinline__ float sigmoidf_(float x) {
    return __fdividef(1.0f, 1.0f + __expf(-x));
}
__device__ __forceinline__ float tanhf_(float x) {
    float ax = fabsf(x);
    float e  = __expf(-2.0f * ax);
    float t  = __fdividef(1.0f - e, 1.0f + e);
    return copysignf(t, x);
}

// K0: zero 64MB output + build weight layouts + fused bias + counters
__global__ void k_boot(float4* __restrict__ out,
                       const float* __restrict__ w_ih, const float* __restrict__ w_hh,
                       const float* __restrict__ b_ih, const float* __restrict__ b_hh) {
    int i = blockIdx.x * blockDim.x + threadIdx.x;
    int stride = gridDim.x * blockDim.x;
    const float4 z = make_float4(0.f, 0.f, 0.f, 0.f);
    for (int t = i; t < OUT_ELEMS/4; t += stride) out[t] = z;
    if (i < CC*GATES) {                        // x-part transposed [k][g]
        int k = i / GATES, g = i % GATES;
        g_WT[i] = w_ih[g*CC + k];
    }
    if (i < K4*4*HID) {                        // multi layout
        int k4 = i / (4*HID);
        int rem = i % (4*HID);
        int q = rem / HID, h = rem % HID;
        int g = q*HID + h;
        float v[4];
        #pragma unroll
        for (int j = 0; j < 4; j++) {
            int k = k4*4 + j;
            v[j] = (k < CC) ? w_ih[g*CC + k] : w_hh[g*HID + (k - CC)];
        }
        g_W4[i] = make_float4(v[0], v[1], v[2], v[3]);
    }
    if (i < GATES) g_bias[i] = b_ih[i] + b_hh[i];
    if (i == 0) { g_ns = 0; g_nm = 0; }
}

// K1: per-batch plan via in-shared counting sort (u16-packed counters).
__global__ void __launch_bounds__(1024) k_plan(const int* __restrict__ coords) {
    __shared__ unsigned int pcnt[RFN/2];     // two u16 counters per int (32KB)
    __shared__ unsigned short srf[NN];
    __shared__ unsigned short sev[NN];
    __shared__ int sscan[1024];
    int b = blockIdx.x, tid = threadIdx.x;

    #pragma unroll
    for (int j = 0; j < 8; j++) pcnt[tid + j*1024] = 0;
    __syncthreads();

    // count (keep this thread's rf ids in regs for the scatter pass)
    int n0 = tid, n1 = tid + 1024;
    int x0 = coords[(b*NN + n0)*2], y0 = coords[(b*NN + n0)*2 + 1];
    int x1 = coords[(b*NN + n1)*2], y1 = coords[(b*NN + n1)*2 + 1];
    int rf0 = y0*128 + x0, rf1 = y1*128 + x1;
    atomicAdd(&pcnt[rf0 >> 1], 1u << ((rf0 & 1)*16));
    atomicAdd(&pcnt[rf1 >> 1], 1u << ((rf1 & 1)*16));
    __syncthreads();

    // exclusive scan over 16384 u16 counts (16 per thread, packed in 8 ints)
    unsigned int ex[8];
    int run = 0;
    #pragma unroll
    for (int j = 0; j < 8; j++) {
        unsigned int v = pcnt[tid*8 + j];
        int c0 = v & 0xFFFF, c1 = v >> 16;
        int e0 = run; run += c0;
        int e1 = run; run += c1;
        ex[j] = (unsigned)e0 | ((unsigned)e1 << 16);
    }
    sscan[tid] = run;
    __syncthreads();
    for (int d = 1; d < 1024; d <<= 1) {
        int v = (tid >= d) ? sscan[tid - d] : 0;
        __syncthreads();
        sscan[tid] += v;
        __syncthreads();
    }
    unsigned int prev = (unsigned)(sscan[tid] - run);
    unsigned int prevp = prev * 0x00010001u;
    #pragma unroll
    for (int j = 0; j < 8; j++) pcnt[tid*8 + j] = ex[j] + prevp;
    __syncthreads();

    // scatter (pcnt now serves as cursors)
    {
        unsigned int p = atomicAdd(&pcnt[rf0 >> 1], 1u << ((rf0 & 1)*16));
        int pos = (p >> ((rf0 & 1)*16)) & 0xFFFF;
        sev[pos] = (unsigned short)n0; srf[pos] = (unsigned short)rf0;
        p = atomicAdd(&pcnt[rf1 >> 1], 1u << ((rf1 & 1)*16));
        pos = (p >> ((rf1 & 1)*16)) & 0xFFFF;
        sev[pos] = (unsigned short)n1; srf[pos] = (unsigned short)rf1;
    }
    __syncthreads();

    // pass A: restore time order inside each bucket (tiny insertion sorts)
    #pragma unroll
    for (int s = 0; s < 2; s++) {
        int i = tid + s*1024;
        int rf = srf[i];
        int pv = (i == 0) ? -1 : (int)srf[i-1];
        if (rf != pv) {
            int L = 1;
            while (i + L < NN && srf[i+L] == rf) L++;
            if (L > 1) {
                for (int a = 1; a < L; a++) {
                    unsigned short v = sev[i+a];
                    int j = a - 1;
                    while (j >= 0 && sev[i+j] > v) { sev[i+j+1] = sev[i+j]; j--; }
                    sev[i+j+1] = v;
                }
            }
        }
    }
    __syncthreads();

    // pass B: emit chain records + dump sorted event ids
    #pragma unroll
    for (int s = 0; s < 2; s++) {
        int i = tid + s*1024;
        g_sorted[b*NN + i] = sev[i];
        int rf = srf[i];
        int pv = (i == 0) ? -1 : (int)srf[i-1];
        bool isb = (rf != pv);
        int L = 0;
        if (isb) {
            L = 1;
            while (i + L < NN && srf[i+L] == rf) L++;
        }
        bool sgl = isb && (L == 1);
        unsigned bal = __ballot_sync(0xffffffffu, sgl);
        if (sgl) {
            int lane = tid & 31;
            int leader = __ffs(bal) - 1;
            int base = 0;
            if (lane == leader) base = atomicAdd(&g_ns, __popc(bal));
            base = __shfl_sync(bal, base, leader);
            g_single[base + __popc(bal & ((1u << lane) - 1))] =
                (int)sev[i] | (b << 11) | (rf << 14);
        } else if (isb) {
            int idx = atomicAdd(&g_nm, 1);
            g_mult[idx] = make_int2(rf | (b << 14) | (i << 17), L);
        }
    }
}

// K2: fused LSTM. Blocks 0..MUL_BLOCKS-1: multi chains (split-K over s=0..3);
// blocks MUL_BLOCKS..: singleton chains (warp = 4 chains, Wx staged in shared).
__global__ void __launch_bounds__(512) k_lstm(const float* __restrict__ feat,
                                              float* __restrict__ out) {
    __shared__ float Ws[CC*GATES];                 // single path (32KB)
    __shared__ float bs[GATES];
    __shared__ float xsh[16][4][CC];
    __shared__ __align__(16) float ivec[2][KTOT];  // multi path

    int tid = threadIdx.x;

    if (blockIdx.x < MUL_BLOCKS) {
        // ---------------- multi-event chains ----------------
        int h = tid >> 2;            // hidden unit 0..127
        int s = tid & 3;             // K-slice 0..3 (9 float4 groups each)
        int nm = g_nm;

        float b0 = g_bias[h],       b1 = g_bias[128 + h];
        float b2 = g_bias[256 + h], b3 = g_bias[384 + h];

        for (int pair = blockIdx.x; 2*pair < nm; pair += MUL_BLOCKS) {
            int2 m0 = g_mult[2*pair];
            int2 m1 = (2*pair + 1 < nm) ? g_mult[2*pair + 1] : make_int2(0, 0);
            int rfA = m0.x & 0x3FFF, bA = (m0.x >> 14) & 7, offA = m0.x >> 17, lenA = m0.y;
            int rfB = m1.x & 0x3FFF, bB = (m1.x >> 14) & 7, offB = m1.x >> 17, lenB = m1.y;
            int maxlen = max(lenA, lenB);

            float cstA = 0.f, cstB = 0.f;

            for (int r = 0; r < maxlen; r++) {
                if (tid < 32) {                     // stage x for both chains
                    int c = tid >> 4, k = tid & 15;
                    int len = c ? lenB : lenA;
                    int off = c ? offB : offA;
                    int bb  = c ? bB   : bA;
                    if (len > r) {
                        int e = g_sorted[bb*NN + off + r];
                        ivec[c][k] = feat[(bb*NN + e)*CC + k];
                    }
                }
                __syncthreads();

                float a0, a1, a2, a3, c0, c1, c2, c3;
                a0 = (s == 0) ? b0 : 0.f;  a1 = (s == 0) ? b1 : 0.f;
                a2 = (s == 0) ? b2 : 0.f;  a3 = (s == 0) ? b3 : 0.f;
                c0 = a0; c1 = a1; c2 = a2; c3 = a3;

                if (r == 0) {
                    if (s == 0) {                    // x-only (h == 0)
                        #pragma unroll
                        for (int k4 = 0; k4 < CC/4; k4++) {
                            float4 iA = *(const float4*)&ivec[0][k4*4];
                            float4 iB = *(const float4*)&ivec[1][k4*4];
                            int base = (k4 << 2)*HID + h;
                            float4 w0 = g_W4[base];
                            float4 w1 = g_W4[base + HID];
                            float4 w2 = g_W4[base + 2*HID];
                            float4 w3 = g_W4[base + 3*HID];
                            a0 += iA.x*w0.x + iA.y*w0.y + iA.z*w0.z + iA.w*w0.w;
                            a1 += iA.x*w1.x + iA.y*w1.y + iA.z*w1.z + iA.w*w1.w;
                            a2 += iA.x*w2.x + iA.y*w2.y + iA.z*w2.z + iA.w*w2.w;
                            a3 += iA.x*w3.x + iA.y*w3.y + iA.z*w3.z + iA.w*w3.w;
                            c0 += iB.x*w0.x + iB.y*w0.y + iB.z*w0.z + iB.w*w0.w;
                            c1 += iB.x*w1.x + iB.y*w1.y + iB.z*w1.z + iB.w*w1.w;
                            c2 += iB.x*w2.x + iB.y*w2.y + iB.z*w2.z + iB.w*w2.w;
                            c3 += iB.x*w3.x + iB.y*w3.y + iB.z*w3.z + iB.w*w3.w;
                        }
                    }
                } else {
                    int k0 = s * 9;                  // this slice's 9 K-groups
                    #pragma unroll
                    for (int j = 0; j < 9; j++) {
                        int k4 = k0 + j;
                        float4 iA = *(const float4*)&ivec[0][k4*4];
                        float4 iB = *(const float4*)&ivec[1][k4*4];
                        int base = (k4 << 2)*HID + h;
                        float4 w0 = g_W4[base];
                        float4 w1 = g_W4[base + HID];
                        float4 w2 = g_W4[base + 2*HID];
                        float4 w3 = g_W4[base + 3*HID];
                        a0 += iA.x*w0.x + iA.y*w0.y + iA.z*w0.z + iA.w*w0.w;
                        a1 += iA.x*w1.x + iA.y*w1.y + iA.z*w1.z + iA.w*w1.w;
                        a2 += iA.x*w2.x + iA.y*w2.y + iA.z*w2.z + iA.w*w2.w;
                        a3 += iA.x*w3.x + iA.y*w3.y + iA.z*w3.z + iA.w*w3.w;
                        c0 += iB.x*w0.x + iB.y*w0.y + iB.z*w0.z + iB.w*w0.w;
                        c1 += iB.x*w1.x + iB.y*w1.y + iB.z*w1.z + iB.w*w1.w;
                        c2 += iB.x*w2.x + iB.y*w2.y + iB.z*w2.z + iB.w*w2.w;
                        c3 += iB.x*w3.x + iB.y*w3.y + iB.z*w3.z + iB.w*w3.w;
                    }
                }
                __syncthreads();                     // all ivec reads done

                // reduce partials across the 4 s-lanes (adjacent in warp)
                a0 += __shfl_xor_sync(0xffffffffu, a0, 1);
                a0 += __shfl_xor_sync(0xffffffffu, a0, 2);
                a1 += __shfl_xor_sync(0xffffffffu, a1, 1);
                a1 += __shfl_xor_sync(0xffffffffu, a1, 2);
                a2 += __shfl_xor_sync(0xffffffffu, a2, 1);
                a2 += __shfl_xor_sync(0xffffffffu, a2, 2);
                a3 += __shfl_xor_sync(0xffffffffu, a3, 1);
                a3 += __shfl_xor_sync(0xffffffffu, a3, 2);
                c0 += __shfl_xor_sync(0xffffffffu, c0, 1);
                c0 += __shfl_xor_sync(0xffffffffu, c0, 2);
                c1 += __shfl_xor_sync(0xffffffffu, c1, 1);
                c1 += __shfl_xor_sync(0xffffffffu, c1, 2);
                c2 += __shfl_xor_sync(0xffffffffu, c2, 1);
                c2 += __shfl_xor_sync(0xffffffffu, c2, 2);
                c3 += __shfl_xor_sync(0xffffffffu, c3, 1);
                c3 += __shfl_xor_sync(0xffffffffu, c3, 2);

                if (lenA > r) {
                    float ig = sigmoidf_(a0), fg = sigmoidf_(a1);
                    float gg = tanhf_(a2),   og = sigmoidf_(a3);
                    cstA = fg*cstA + ig*gg;
                    float hn = og * tanhf_(cstA);
                    if (r == lenA - 1) {
                        if (s == 0) {
                            int y = rfA >> 7, x = rfA & 127;
                            out[((bA*HID + h)*128 + y)*128 + x] = hn;
                        }
                    } else if (s == 0) {
                        ivec[0][CC + h] = hn;
                    }
                }
                if (lenB > r) {
                    float ig = sigmoidf_(c0), fg = sigmoidf_(c1);
                    float gg = tanhf_(c2),   og = sigmoidf_(c3);
                    cstB = fg*cstB + ig*gg;
                    float hn = og * tanhf_(cstB);
                    if (r == lenB - 1) {
                        if (s == 0) {
                            int y = rfB >> 7, x = rfB & 127;
                            out[((bB*HID + h)*128 + y)*128 + x] = hn;
                        }
                    } else if (s == 0) {
                        ivec[1][CC + h] = hn;
                    }
                }
                __syncthreads();                     // h writes before next read
            }
        }
    } else {
        // ---------------- singleton chains ----------------
        int lane = tid & 31, warp = tid >> 5;
        int ns = g_ns;

        for (int i = tid; i < CC*GATES; i += 512) Ws[i] = g_WT[i];
        for (int i = tid; i < GATES; i += 512) bs[i] = g_bias[i];
        __syncthreads();

        int idx0 = (blockIdx.x - MUL_BLOCKS) * 64 + (warp << 2);
        if (idx0 >= ns) return;

        int rec = -1;
        if (lane < 4 && idx0 + lane < ns) rec = g_single[idx0 + lane];

        #pragma unroll
        for (int s2 = 0; s2 < 2; s2++) {
            int slot = lane + (s2 << 5);
            int c = slot >> 4, k = slot & 15;
            int rc = __shfl_sync(0xffffffffu, rec, c);
            if (rc >= 0) {
                int ev = rc & 2047, bb = (rc >> 11) & 7;
                xsh[warp][c][k] = feat[(bb*NN + ev)*CC + k];
            }
        }
        __syncwarp();

        float acc[4][16];
        #pragma unroll
        for (int q = 0; q < 4; q++) {
            float4 bv = *(const float4*)&bs[q*128 + (lane << 2)];
            #pragma unroll
            for (int c = 0; c < 4; c++) {
                acc[c][q*4+0] = bv.x; acc[c][q*4+1] = bv.y;
                acc[c][q*4+2] = bv.z; acc[c][q*4+3] = bv.w;
            }
        }
        #pragma unroll
        for (int k = 0; k < CC; k++) {
            const float* wk = Ws + k*GATES + (lane << 2);
            float4 w0 = *(const float4*)(wk);
            float4 w1 = *(const float4*)(wk + 128);
            float4 w2 = *(const float4*)(wk + 256);
            float4 w3 = *(const float4*)(wk + 384);
            #pragma unroll
            for (int c = 0; c < 4; c++) {
                float iv = xsh[warp][c][k];
                acc[c][0]  += iv*w0.x; acc[c][1]  += iv*w0.y; acc[c][2]  += iv*w0.z; acc[c][3]  += iv*w0.w;
                acc[c][4]  += iv*w1.x; acc[c][5]  += iv*w1.y; acc[c][6]  += iv*w1.z; acc[c][7]  += iv*w1.w;
                acc[c][8]  += iv*w2.x; acc[c][9]  += iv*w2.y; acc[c][10] += iv*w2.z; acc[c][11] += iv*w2.w;
                acc[c][12] += iv*w3.x; acc[c][13] += iv*w3.y; acc[c][14] += iv*w3.z; acc[c][15] += iv*w3.w;
            }
        }
        #pragma unroll
        for (int c = 0; c < 4; c++) {
            int rc = __shfl_sync(0xffffffffu, rec, c);
            if (rc >= 0) {
                int bb = (rc >> 11) & 7, rf = rc >> 14;
                int y = rf >> 7, x = rf & 127;
                #pragma unroll
                for (int i = 0; i < 4; i++) {
                    float cn = sigmoidf_(acc[c][0 + i]) * tanhf_(acc[c][8 + i]);  // c_prev=0
                    float hh = sigmoidf_(acc[c][12 + i]) * tanhf_(cn);
                    out[((bb*HID + (lane << 2) + i)*128 + y)*128 + x] = hh;
                }
            }
        }
    }
}

extern "C" void kernel_launch(void* const* d_in, const int* in_sizes, int n_in,
                              void* d_out, int out_size) {
    const float* features = (const float*)d_in[0];
    const int*   coords   = (const int*)  d_in[1];
    const float* w_ih     = (const float*)d_in[2];
    const float* w_hh     = (const float*)d_in[3];
    const float* b_ih     = (const float*)d_in[4];
    const float* b_hh     = (const float*)d_in[5];
    float* out = (float*)d_out;

    k_boot<<<4096, 256>>>((float4*)out, w_ih, w_hh, b_ih, b_hh);
    k_plan<<<BB, 1024>>>(coords);
    k_lstm<<<LSTM_GRID, 512>>>(features, out);
}

// round 7
// speedup vs baseline: 3.9142x; 1.3535x over previous
#include <cuda_runtime.h>

// Problem constants (fixed by the dataset reference)
#define BB   8
#define NN   2048
#define CC   16
#define HID  128
#define RFN  16384      // 128*128 receptive fields
#define KTOT 144        // C + HID
#define GATES 512       // 4*HID
#define K4   (KTOT/4)   // 36 float4 groups along K
#define OUT_ELEMS (BB*HID*128*128)

#define PLAN_BLOCKS 8
#define PREP_GRID   520
#define MUL_BLOCKS  128   // 16 per batch
#define SGL_BLOCKS  256   // 32 per batch
#define LSTM_GRID   (MUL_BLOCKS + SGL_BLOCKS)
#define CM          8     // multi chains per block

// ---------------- device scratch (no allocations allowed) ----------------
__device__ int    g_sorted[BB*NN];     // per batch: event ids sorted by (rf, time)
__device__ int    g_single[BB*NN];     // per batch: ev | rf<<11
__device__ int2   g_mult[BB*NN];       // per batch: {rf | off<<14, len}
__device__ int    g_ns[BB], g_nm[BB];
__device__ float  g_WT[CC*GATES];      // x-part weights, [k][gate] (singles)
__device__ float4 g_W4[K4*4*HID];      // [(k4*4+q)*128 + h] = W[q*128+h][4k4..4k4+3]
__device__ float  g_bias[GATES];

// ---------------- helpers ----------------
__device__ __forceinline__ float sigmoidf_(float x) {
    return __fdividef(1.0f, 1.0f + __expf(-x));
}
__device__ __forceinline__ float tanhf_(float x) {
    float ax = fabsf(x);
    float e  = __expf(-2.0f * ax);
    float t  = __fdividef(1.0f - e, 1.0f + e);
    return copysignf(t, x);
}

// K0: fused prep. Blocks 0..7: per-batch plan (counting sort + chain lists).
// Blocks 8..: zero 64MB output + build weight layouts (runs concurrently).
__global__ void __launch_bounds__(1024) k_prep(float4* __restrict__ out,
                       const int* __restrict__ coords,
                       const float* __restrict__ w_ih, const float* __restrict__ w_hh,
                       const float* __restrict__ b_ih, const float* __restrict__ b_hh) {
    __shared__ unsigned int pcnt[RFN/2];     // two u16 counters per int (32KB)
    __shared__ unsigned short srf[NN];
    __shared__ unsigned short sev[NN];
    __shared__ int sscan[1024];
    int tid = threadIdx.x;

    if (blockIdx.x >= PLAN_BLOCKS) {
        // ---- fill + weight path ----
        int i = (blockIdx.x - PLAN_BLOCKS)*1024 + tid;
        int stride = (PREP_GRID - PLAN_BLOCKS)*1024;
        const float4 z = make_float4(0.f, 0.f, 0.f, 0.f);
        for (int t = i; t < OUT_ELEMS/4; t += stride) out[t] = z;
        for (int t = i; t < CC*GATES; t += stride) {
            int k = t / GATES, g = t % GATES;
            g_WT[t] = w_ih[g*CC + k];
        }
        for (int t = i; t < K4*4*HID; t += stride) {
            int k4 = t / (4*HID);
            int rem = t % (4*HID);
            int q = rem / HID, h = rem % HID;
            int g = q*HID + h;
            float v[4];
            #pragma unroll
            for (int j = 0; j < 4; j++) {
                int k = k4*4 + j;
                v[j] = (k < CC) ? w_ih[g*CC + k] : w_hh[g*HID + (k - CC)];
            }
            g_W4[t] = make_float4(v[0], v[1], v[2], v[3]);
        }
        for (int t = i; t < GATES; t += stride) g_bias[t] = b_ih[t] + b_hh[t];
        return;
    }

    // ---- plan path (one block per batch) ----
    int b = blockIdx.x;
    if (tid == 0) { g_ns[b] = 0; g_nm[b] = 0; }
    #pragma unroll
    for (int j = 0; j < 8; j++) pcnt[tid + j*1024] = 0;
    __syncthreads();

    // count (keep this thread's rf ids in regs for the scatter pass)
    int n0 = tid, n1 = tid + 1024;
    int x0 = coords[(b*NN + n0)*2], y0 = coords[(b*NN + n0)*2 + 1];
    int x1 = coords[(b*NN + n1)*2], y1 = coords[(b*NN + n1)*2 + 1];
    int rf0 = y0*128 + x0, rf1 = y1*128 + x1;
    atomicAdd(&pcnt[rf0 >> 1], 1u << ((rf0 & 1)*16));
    atomicAdd(&pcnt[rf1 >> 1], 1u << ((rf1 & 1)*16));
    __syncthreads();

    // exclusive scan over 16384 u16 counts (16 per thread, packed in 8 ints)
    unsigned int ex[8];
    int run = 0;
    #pragma unroll
    for (int j = 0; j < 8; j++) {
        unsigned int v = pcnt[tid*8 + j];
        int c0 = v & 0xFFFF, c1 = v >> 16;
        int e0 = run; run += c0;
        int e1 = run; run += c1;
        ex[j] = (unsigned)e0 | ((unsigned)e1 << 16);
    }
    sscan[tid] = run;
    __syncthreads();
    for (int d = 1; d < 1024; d <<= 1) {
        int v = (tid >= d) ? sscan[tid - d] : 0;
        __syncthreads();
        sscan[tid] += v;
        __syncthreads();
    }
    unsigned int prev = (unsigned)(sscan[tid] - run);
    unsigned int prevp = prev * 0x00010001u;
    #pragma unroll
    for (int j = 0; j < 8; j++) pcnt[tid*8 + j] = ex[j] + prevp;
    __syncthreads();

    // scatter (pcnt now serves as cursors)
    {
        unsigned int p = atomicAdd(&pcnt[rf0 >> 1], 1u << ((rf0 & 1)*16));
        int pos = (p >> ((rf0 & 1)*16)) & 0xFFFF;
        sev[pos] = (unsigned short)n0; srf[pos] = (unsigned short)rf0;
        p = atomicAdd(&pcnt[rf1 >> 1], 1u << ((rf1 & 1)*16));
        pos = (p >> ((rf1 & 1)*16)) & 0xFFFF;
        sev[pos] = (unsigned short)n1; srf[pos] = (unsigned short)rf1;
    }
    __syncthreads();

    // pass A: restore time order inside each bucket (tiny insertion sorts)
    #pragma unroll
    for (int s = 0; s < 2; s++) {
        int i = tid + s*1024;
        int rf = srf[i];
        int pv = (i == 0) ? -1 : (int)srf[i-1];
        if (rf != pv) {
            int L = 1;
            while (i + L < NN && srf[i+L] == rf) L++;
            if (L > 1) {
                for (int a = 1; a < L; a++) {
                    unsigned short v = sev[i+a];
                    int j = a - 1;
                    while (j >= 0 && sev[i+j] > v) { sev[i+j+1] = sev[i+j]; j--; }
                    sev[i+j+1] = v;
                }
            }
        }
    }
    __syncthreads();

    // pass B: emit chain records + dump sorted event ids
    #pragma unroll
    for (int s = 0; s < 2; s++) {
        int i = tid + s*1024;
        g_sorted[b*NN + i] = sev[i];
        int rf = srf[i];
        int pv = (i == 0) ? -1 : (int)srf[i-1];
        bool isb = (rf != pv);
        int L = 0;
        if (isb) {
            L = 1;
            while (i + L < NN && srf[i+L] == rf) L++;
        }
        bool sgl = isb && (L == 1);
        unsigned bal = __ballot_sync(0xffffffffu, sgl);
        if (sgl) {
            int lane = tid & 31;
            int leader = __ffs(bal) - 1;
            int base = 0;
            if (lane == leader) base = atomicAdd(&g_ns[b], __popc(bal));
            base = __shfl_sync(bal, base, leader);
            g_single[b*NN + base + __popc(bal & ((1u << lane) - 1))] =
                (int)sev[i] | (rf << 11);
        } else if (isb) {
            int idx = atomicAdd(&g_nm[b], 1);
            g_mult[b*NN + idx] = make_int2(rf | (i << 14), L);
        }
    }
}

// K1: fused LSTM.
// Blocks 0..MUL_BLOCKS-1: multi chains, 8 chains/block, split-K over s=0..3.
// Blocks MUL_BLOCKS..: singleton chains (warp = 4 chains, Wx staged in shared).
__global__ void __launch_bounds__(512) k_lstm(const float* __restrict__ feat,
                                              float* __restrict__ out) {
    __shared__ float Ws[CC*GATES];                  // single path (32KB)
    __shared__ float bs[GATES];
    __shared__ float xsh[16][4][CC];
    __shared__ __align__(16) float ivec[CM][KTOT];  // multi path [chain][x|h]
    __shared__ int slen[CM], soff[CM];
    __shared__ int2 mds[CM];

    int tid = threadIdx.x;

    if (blockIdx.x < MUL_BLOCKS) {
        // ---------------- multi-event chains ----------------
        int bb  = blockIdx.x & 7;
        int sub = blockIdx.x >> 3;          // 0..15
        int h = tid >> 2;                   // hidden unit 0..127
        int s = tid & 3;                    // K slice 0..3 (9 float4-groups each)
        int nm = g_nm[bb];

        float b0 = g_bias[h],       b1 = g_bias[128 + h];
        float b2 = g_bias[256 + h], b3 = g_bias[384 + h];

        for (int grp = sub*CM; grp < nm; grp += 16*CM) {
            if (tid < CM) {
                int ci = grp + tid;
                int2 m = (ci < nm) ? g_mult[bb*NN + ci] : make_int2(0, 0);
                mds[tid] = m;
                slen[tid] = m.y;
                soff[tid] = m.x >> 14;
            }
            __syncthreads();
            int rf[CM], len[CM];
            int maxlen = 0;
            #pragma unroll
            for (int c = 0; c < CM; c++) {
                int2 m = mds[c];
                rf[c] = m.x & 0x3FFF;
                len[c] = m.y;
                maxlen = max(maxlen, len[c]);
            }
            float cst[CM];
            #pragma unroll
            for (int c = 0; c < CM; c++) cst[c] = 0.f;

            for (int r = 0; r < maxlen; r++) {
                if (tid < CM*CC) {                 // stage x for the 8 chains
                    int c = tid >> 4, k = tid & 15;
                    if (slen[c] > r) {
                        int e = g_sorted[bb*NN + soff[c] + r];
                        ivec[c][k] = feat[(bb*NN + e)*CC + k];
                    }
                }
                __syncthreads();

                float a[CM][4];
                #pragma unroll
                for (int c = 0; c < CM; c++) {
                    a[c][0] = (s == 0) ? b0 : 0.f;
                    a[c][1] = (s == 0) ? b1 : 0.f;
                    a[c][2] = (s == 0) ? b2 : 0.f;
                    a[c][3] = (s == 0) ? b3 : 0.f;
                }

                if (r == 0) {
                    if (s == 0) {                  // x-only (h == 0)
                        #pragma unroll
                        for (int k4 = 0; k4 < CC/4; k4++) {
                            int base = (k4 << 2)*HID + h;
                            float4 w0 = g_W4[base];
                            float4 w1 = g_W4[base + HID];
                            float4 w2 = g_W4[base + 2*HID];
                            float4 w3 = g_W4[base + 3*HID];
                            #pragma unroll
                            for (int c = 0; c < CM; c++) {
                                float4 iv = *(const float4*)&ivec[c][k4*4];
                                a[c][0] += iv.x*w0.x + iv.y*w0.y + iv.z*w0.z + iv.w*w0.w;
                                a[c][1] += iv.x*w1.x + iv.y*w1.y + iv.z*w1.z + iv.w*w1.w;
                                a[c][2] += iv.x*w2.x + iv.y*w2.y + iv.z*w2.z + iv.w*w2.w;
                                a[c][3] += iv.x*w3.x + iv.y*w3.y + iv.z*w3.z + iv.w*w3.w;
                            }
                        }
                    }
                } else {
                    #pragma unroll
                    for (int j = 0; j < 9; j++) {
                        int k4 = s*9 + j;
                        int base = (k4 << 2)*HID + h;
                        float4 w0 = g_W4[base];
                        float4 w1 = g_W4[base + HID];
                        float4 w2 = g_W4[base + 2*HID];
                        float4 w3 = g_W4[base + 3*HID];
                        #pragma unroll
                        for (int c = 0; c < CM; c++) {
                            float4 iv = *(const float4*)&ivec[c][k4*4];
                            a[c][0] += iv.x*w0.x + iv.y*w0.y + iv.z*w0.z + iv.w*w0.w;
                            a[c][1] += iv.x*w1.x + iv.y*w1.y + iv.z*w1.z + iv.w*w1.w;
                            a[c][2] += iv.x*w2.x + iv.y*w2.y + iv.z*w2.z + iv.w*w2.w;
                            a[c][3] += iv.x*w3.x + iv.y*w3.y + iv.z*w3.z + iv.w*w3.w;
                        }
                    }
                }
                __syncthreads();                   // all ivec reads done

                // reduce partials across the 4 s-lanes (adjacent in warp)
                #pragma unroll
                for (int c = 0; c < CM; c++) {
                    #pragma unroll
                    for (int q = 0; q < 4; q++) {
                        a[c][q] += __shfl_xor_sync(0xffffffffu, a[c][q], 1);
                        a[c][q] += __shfl_xor_sync(0xffffffffu, a[c][q], 2);
                    }
                }

                #pragma unroll
                for (int c = 0; c < CM; c++) {
                    if (len[c] > r) {
                        float ig = sigmoidf_(a[c][0]), fg = sigmoidf_(a[c][1]);
                        float gg = tanhf_(a[c][2]),   og = sigmoidf_(a[c][3]);
                        cst[c] = fg*cst[c] + ig*gg;
                        float hn = og * tanhf_(cst[c]);
                        if (s == 0) {
                            if (r == len[c] - 1) {
                                int y = rf[c] >> 7, x = rf[c] & 127;
                                out[((bb*HID + h)*128 + y)*128 + x] = hn;
                            } else {
                                ivec[c][CC + h] = hn;
                            }
                        }
                    }
                }
                // next iteration's first __syncthreads orders h writes vs reads
            }
            __syncthreads();   // done with slen/soff/ivec before next grp reload
        }
    } else {
        // ---------------- singleton chains ----------------
        int lane = tid & 31, warp = tid >> 5;
        int sidx = blockIdx.x - MUL_BLOCKS;
        int bb = sidx & 7;
        int sg = sidx >> 3;                 // 0..31
        int ns = g_ns[bb];

        for (int i = tid; i < CC*GATES; i += 512) Ws[i] = g_WT[i];
        for (int i = tid; i < GATES; i += 512) bs[i] = g_bias[i];
        __syncthreads();

        int idx0 = sg*64 + (warp << 2);
        if (idx0 >= ns) return;

        int rec = -1;
        if (lane < 4 && idx0 + lane < ns) rec = g_single[bb*NN + idx0 + lane];

        #pragma unroll
        for (int s2 = 0; s2 < 2; s2++) {
            int slot = lane + (s2 << 5);
            int c = slot >> 4, k = slot & 15;
            int rc = __shfl_sync(0xffffffffu, rec, c);
            if (rc >= 0) {
                int ev = rc & 2047;
                xsh[warp][c][k] = feat[(bb*NN + ev)*CC + k];
            }
        }
        __syncwarp();

        float acc[4][16];
        #pragma unroll
        for (int q = 0; q < 4; q++) {
            float4 bv = *(const float4*)&bs[q*128 + (lane << 2)];
            #pragma unroll
            for (int c = 0; c < 4; c++) {
                acc[c][q*4+0] = bv.x; acc[c][q*4+1] = bv.y;
                acc[c][q*4+2] = bv.z; acc[c][q*4+3] = bv.w;
            }
        }
        #pragma unroll
        for (int k = 0; k < CC; k++) {
            const float* wk = Ws + k*GATES + (lane << 2);
            float4 w0 = *(const float4*)(wk);
            float4 w1 = *(const float4*)(wk + 128);
            float4 w2 = *(const float4*)(wk + 256);
            float4 w3 = *(const float4*)(wk + 384);
            #pragma unroll
            for (int c = 0; c < 4; c++) {
                float iv = xsh[warp][c][k];
                acc[c][0]  += iv*w0.x; acc[c][1]  += iv*w0.y; acc[c][2]  += iv*w0.z; acc[c][3]  += iv*w0.w;
                acc[c][4]  += iv*w1.x; acc[c][5]  += iv*w1.y; acc[c][6]  += iv*w1.z; acc[c][7]  += iv*w1.w;
                acc[c][8]  += iv*w2.x; acc[c][9]  += iv*w2.y; acc[c][10] += iv*w2.z; acc[c][11] += iv*w2.w;
                acc[c][12] += iv*w3.x; acc[c][13] += iv*w3.y; acc[c][14] += iv*w3.z; acc[c][15] += iv*w3.w;
            }
        }
        #pragma unroll
        for (int c = 0; c < 4; c++) {
            int rc = __shfl_sync(0xffffffffu, rec, c);
            if (rc >= 0) {
                int rf = rc >> 11;
                int y = rf >> 7, x = rf & 127;
                #pragma unroll
                for (int i = 0; i < 4; i++) {
                    float cn = sigmoidf_(acc[c][0 + i]) * tanhf_(acc[c][8 + i]);  // c_prev=0
                    float hh = sigmoidf_(acc[c][12 + i]) * tanhf_(cn);
                    out[((bb*HID + (lane << 2) + i)*128 + y)*128 + x] = hh;
                }
            }
        }
    }
}

extern "C" void kernel_launch(void* const* d_in, const int* in_sizes, int n_in,
                              void* d_out, int out_size) {
    const float* features = (const float*)d_in[0];
    const int*   coords   = (const int*)  d_in[1];
    const float* w_ih     = (const float*)d_in[2];
    const float* w_hh     = (const float*)d_in[3];
    const float* b_ih     = (const float*)d_in[4];
    const float* b_hh     = (const float*)d_in[5];
    float* out = (float*)d_out;

    k_prep<<<PREP_GRID, 1024>>>((float4*)out, coords, w_ih, w_hh, b_ih, b_hh);
    k_lstm<<<LSTM_GRID, 512>>>(features, out);
}

// round 8
// speedup vs baseline: 3.9331x; 1.0048x over previous
#include <cuda_runtime.h>

// Problem constants (fixed by the dataset reference)
#define BB   8
#define NN   2048
#define CC   16
#define HID  128
#define RFN  16384      // 128*128 receptive fields
#define KTOT 144        // C + HID
#define GATES 512       // 4*HID
#define K4   (KTOT/4)   // 36 float4 groups along K
#define OUT_ELEMS (BB*HID*128*128)

#define PLAN_BLOCKS 8
#define PREP_GRID   520
#define MUL_BLOCKS  128   // 16 per batch
#define SGL_BLOCKS  168   // 21 per batch
#define LSTM_GRID   (MUL_BLOCKS + SGL_BLOCKS)
#define CM          8     // multi chains per block

// ---------------- device scratch (no allocations allowed) ----------------
__device__ int    g_sorted[BB*NN];     // per batch: event ids sorted by (rf, time)
__device__ int    g_single[BB*NN];     // per batch: ev | rf<<11
__device__ int2   g_mult[BB*NN];       // per batch: {rf | off<<14, len}
__device__ int    g_ns[BB], g_nm[BB];
__device__ float  g_WT[CC*GATES];      // x-part weights, [k][gate] (singles)
__device__ float4 g_W4[K4*4*HID];      // [(k4*4+q)*128 + h] = W[q*128+h][4k4..4k4+3]
__device__ float  g_bias[GATES];

// ---------------- helpers ----------------
__device__ __forceinline__ float sigmoidf_(float x) {
    return __fdividef(1.0f, 1.0f + __expf(-x));
}
__device__ __forceinline__ float tanhf_(float x) {
    float ax = fabsf(x);
    float e  = __expf(-2.0f * ax);
    float t  = __fdividef(1.0f - e, 1.0f + e);
    return copysignf(t, x);
}
__device__ __forceinline__ unsigned long long dup2_(float v) {
    unsigned long long r;
    asm("mov.b64 %0, {%1, %1};" : "=l"(r) : "f"(v));
    return r;
}
__device__ __forceinline__ void fma2_(unsigned long long& d, unsigned long long a,
                                      unsigned long long b) {
    asm("fma.rn.f32x2 %0, %1, %2, %3;" : "=l"(d) : "l"(a), "l"(b), "l"(d));
}
__device__ __forceinline__ float2 unpack2_(unsigned long long v) {
    float2 r;
    asm("mov.b64 {%0, %1}, %2;" : "=f"(r.x), "=f"(r.y) : "l"(v));
    return r;
}

// K0: fused prep. Blocks 0..7: per-batch plan (counting sort + chain lists).
// Blocks 8..: zero 64MB output + build weight layouts (runs concurrently).
__global__ void __launch_bounds__(1024) k_prep(float4* __restrict__ out,
                       const int* __restrict__ coords,
                       const float* __restrict__ w_ih, const float* __restrict__ w_hh,
                       const float* __restrict__ b_ih, const float* __restrict__ b_hh) {
    __shared__ unsigned int pcnt[RFN/2];     // two u16 counters per int (32KB)
    __shared__ unsigned short srf[NN];
    __shared__ unsigned short sev[NN];
    __shared__ int sscan[1024];
    int tid = threadIdx.x;

    if (blockIdx.x >= PLAN_BLOCKS) {
        // ---- fill + weight path ----
        int i = (blockIdx.x - PLAN_BLOCKS)*1024 + tid;
        int stride = (PREP_GRID - PLAN_BLOCKS)*1024;
        const float4 z = make_float4(0.f, 0.f, 0.f, 0.f);
        for (int t = i; t < OUT_ELEMS/4; t += stride) out[t] = z;
        for (int t = i; t < CC*GATES; t += stride) {
            int k = t / GATES, g = t % GATES;
            g_WT[t] = w_ih[g*CC + k];
        }
        for (int t = i; t < K4*4*HID; t += stride) {
            int k4 = t / (4*HID);
            int rem = t % (4*HID);
            int q = rem / HID, h = rem % HID;
            int g = q*HID + h;
            float v[4];
            #pragma unroll
            for (int j = 0; j < 4; j++) {
                int k = k4*4 + j;
                v[j] = (k < CC) ? w_ih[g*CC + k] : w_hh[g*HID + (k - CC)];
            }
            g_W4[t] = make_float4(v[0], v[1], v[2], v[3]);
        }
        for (int t = i; t < GATES; t += stride) g_bias[t] = b_ih[t] + b_hh[t];
        return;
    }

    // ---- plan path (one block per batch) ----
    int b = blockIdx.x;
    if (tid == 0) { g_ns[b] = 0; g_nm[b] = 0; }
    #pragma unroll
    for (int j = 0; j < 8; j++) pcnt[tid + j*1024] = 0;
    __syncthreads();

    int n0 = tid, n1 = tid + 1024;
    int x0 = coords[(b*NN + n0)*2], y0 = coords[(b*NN + n0)*2 + 1];
    int x1 = coords[(b*NN + n1)*2], y1 = coords[(b*NN + n1)*2 + 1];
    int rf0 = y0*128 + x0, rf1 = y1*128 + x1;
    atomicAdd(&pcnt[rf0 >> 1], 1u << ((rf0 & 1)*16));
    atomicAdd(&pcnt[rf1 >> 1], 1u << ((rf1 & 1)*16));
    __syncthreads();

    unsigned int ex[8];
    int run = 0;
    #pragma unroll
    for (int j = 0; j < 8; j++) {
        unsigned int v = pcnt[tid*8 + j];
        int c0 = v & 0xFFFF, c1 = v >> 16;
        int e0 = run; run += c0;
        int e1 = run; run += c1;
        ex[j] = (unsigned)e0 | ((unsigned)e1 << 16);
    }
    sscan[tid] = run;
    __syncthreads();
    for (int d = 1; d < 1024; d <<= 1) {
        int v = (tid >= d) ? sscan[tid - d] : 0;
        __syncthreads();
        sscan[tid] += v;
        __syncthreads();
    }
    unsigned int prev = (unsigned)(sscan[tid] - run);
    unsigned int prevp = prev * 0x00010001u;
    #pragma unroll
    for (int j = 0; j < 8; j++) pcnt[tid*8 + j] = ex[j] + prevp;
    __syncthreads();

    {
        unsigned int p = atomicAdd(&pcnt[rf0 >> 1], 1u << ((rf0 & 1)*16));
        int pos = (p >> ((rf0 & 1)*16)) & 0xFFFF;
        sev[pos] = (unsigned short)n0; srf[pos] = (unsigned short)rf0;
        p = atomicAdd(&pcnt[rf1 >> 1], 1u << ((rf1 & 1)*16));
        pos = (p >> ((rf1 & 1)*16)) & 0xFFFF;
        sev[pos] = (unsigned short)n1; srf[pos] = (unsigned short)rf1;
    }
    __syncthreads();

    // pass A: restore time order inside each bucket (tiny insertion sorts)
    #pragma unroll
    for (int s = 0; s < 2; s++) {
        int i = tid + s*1024;
        int rf = srf[i];
        int pv = (i == 0) ? -1 : (int)srf[i-1];
        if (rf != pv) {
            int L = 1;
            while (i + L < NN && srf[i+L] == rf) L++;
            if (L > 1) {
                for (int a = 1; a < L; a++) {
                    unsigned short v = sev[i+a];
                    int j = a - 1;
                    while (j >= 0 && sev[i+j] > v) { sev[i+j+1] = sev[i+j]; j--; }
                    sev[i+j+1] = v;
                }
            }
        }
    }
    __syncthreads();

    // pass B: emit chain records + dump sorted event ids
    #pragma unroll
    for (int s = 0; s < 2; s++) {
        int i = tid + s*1024;
        g_sorted[b*NN + i] = sev[i];
        int rf = srf[i];
        int pv = (i == 0) ? -1 : (int)srf[i-1];
        bool isb = (rf != pv);
        int L = 0;
        if (isb) {
            L = 1;
            while (i + L < NN && srf[i+L] == rf) L++;
        }
        bool sgl = isb && (L == 1);
        unsigned bal = __ballot_sync(0xffffffffu, sgl);
        if (sgl) {
            int lane = tid & 31;
            int leader = __ffs(bal) - 1;
            int base = 0;
            if (lane == leader) base = atomicAdd(&g_ns[b], __popc(bal));
            base = __shfl_sync(bal, base, leader);
            g_single[b*NN + base + __popc(bal & ((1u << lane) - 1))] =
                (int)sev[i] | (rf << 11);
        } else if (isb) {
            int idx = atomicAdd(&g_nm[b], 1);
            g_mult[b*NN + idx] = make_int2(rf | (i << 14), L);
        }
    }
}

// K1: fused LSTM, 256-thread blocks, 2 blocks/SM, grid = 296 = one full wave.
// Blocks 0..127: multi chains (CM=8, split-K s∈{0,1} of 18 K-groups each).
// Blocks 128..: singleton chains (8 warps x 4 chains, FFMA2, Wx in shared).
__global__ void __launch_bounds__(256, 2) k_lstm(const float* __restrict__ feat,
                                                 float* __restrict__ out) {
    __shared__ float Ws[CC*GATES];                  // singles path (32KB)
    __shared__ float bs[GATES];
    __shared__ float xsh[8][4][CC];
    __shared__ __align__(16) float ivec[CM][KTOT];  // multi path [chain][x|h]
    __shared__ int slen[CM], soff[CM];
    __shared__ int2 mds[CM];

    int tid = threadIdx.x;

    if (blockIdx.x < MUL_BLOCKS) {
        // ---------------- multi-event chains ----------------
        int bb  = blockIdx.x & 7;
        int sub = blockIdx.x >> 3;          // 0..15
        int h = tid >> 1;                   // hidden unit 0..127
        int s = tid & 1;                    // K slice 0..1 (18 float4-groups each)
        int nm = g_nm[bb];

        float b0 = g_bias[h],       b1 = g_bias[128 + h];
        float b2 = g_bias[256 + h], b3 = g_bias[384 + h];

        for (int grp = sub*CM; grp < nm; grp += 16*CM) {
            if (tid < CM) {
                int ci = grp + tid;
                int2 m = (ci < nm) ? g_mult[bb*NN + ci] : make_int2(0, 0);
                mds[tid] = m;
                slen[tid] = m.y;
                soff[tid] = m.x >> 14;
            }
            __syncthreads();
            int rf[CM], len[CM];
            int maxlen = 0;
            #pragma unroll
            for (int c = 0; c < CM; c++) {
                int2 m = mds[c];
                rf[c] = m.x & 0x3FFF;
                len[c] = m.y;
                maxlen = max(maxlen, len[c]);
            }
            float cst[CM];
            #pragma unroll
            for (int c = 0; c < CM; c++) cst[c] = 0.f;

            for (int r = 0; r < maxlen; r++) {
                if (tid < CM*CC) {                 // stage x for the 8 chains
                    int c = tid >> 4, k = tid & 15;
                    if (slen[c] > r) {
                        int e = g_sorted[bb*NN + soff[c] + r];
                        ivec[c][k] = feat[(bb*NN + e)*CC + k];
                    }
                }
                __syncthreads();

                float a[CM][4];
                #pragma unroll
                for (int c = 0; c < CM; c++) {
                    a[c][0] = (s == 0) ? b0 : 0.f;
                    a[c][1] = (s == 0) ? b1 : 0.f;
                    a[c][2] = (s == 0) ? b2 : 0.f;
                    a[c][3] = (s == 0) ? b3 : 0.f;
                }

                if (r == 0) {
                    if (s == 0) {                  // x-only (h == 0)
                        #pragma unroll
                        for (int k4 = 0; k4 < CC/4; k4++) {
                            int base = (k4 << 2)*HID + h;
                            float4 w0 = g_W4[base];
                            float4 w1 = g_W4[base + HID];
                            float4 w2 = g_W4[base + 2*HID];
                            float4 w3 = g_W4[base + 3*HID];
                            #pragma unroll
                            for (int c = 0; c < CM; c++) {
                                float4 iv = *(const float4*)&ivec[c][k4*4];
                                a[c][0] += iv.x*w0.x + iv.y*w0.y + iv.z*w0.z + iv.w*w0.w;
                                a[c][1] += iv.x*w1.x + iv.y*w1.y + iv.z*w1.z + iv.w*w1.w;
                                a[c][2] += iv.x*w2.x + iv.y*w2.y + iv.z*w2.z + iv.w*w2.w;
                                a[c][3] += iv.x*w3.x + iv.y*w3.y + iv.z*w3.z + iv.w*w3.w;
                            }
                        }
                    }
                } else {
                    #pragma unroll 3
                    for (int j = 0; j < 18; j++) {
                        int k4 = s*18 + j;
                        int base = (k4 << 2)*HID + h;
                        float4 w0 = g_W4[base];
                        float4 w1 = g_W4[base + HID];
                        float4 w2 = g_W4[base + 2*HID];
                        float4 w3 = g_W4[base + 3*HID];
                        #pragma unroll
                        for (int c = 0; c < CM; c++) {
                            float4 iv = *(const float4*)&ivec[c][k4*4];
                            a[c][0] += iv.x*w0.x + iv.y*w0.y + iv.z*w0.z + iv.w*w0.w;
                            a[c][1] += iv.x*w1.x + iv.y*w1.y + iv.z*w1.z + iv.w*w1.w;
                            a[c][2] += iv.x*w2.x + iv.y*w2.y + iv.z*w2.z + iv.w*w2.w;
                            a[c][3] += iv.x*w3.x + iv.y*w3.y + iv.z*w3.z + iv.w*w3.w;
                        }
                    }
                }
                __syncthreads();                   // all ivec reads done

                // reduce partials across the 2 s-lanes (adjacent in warp)
                #pragma unroll
                for (int c = 0; c < CM; c++) {
                    #pragma unroll
                    for (int q = 0; q < 4; q++)
                        a[c][q] += __shfl_xor_sync(0xffffffffu, a[c][q], 1);
                }

                #pragma unroll
                for (int c = 0; c < CM; c++) {
                    if (len[c] > r) {
                        float ig = sigmoidf_(a[c][0]), fg = sigmoidf_(a[c][1]);
                        float gg = tanhf_(a[c][2]),   og = sigmoidf_(a[c][3]);
                        cst[c] = fg*cst[c] + ig*gg;
                        float hn = og * tanhf_(cst[c]);
                        if (s == 0) {
                            if (r == len[c] - 1) {
                                int y = rf[c] >> 7, x = rf[c] & 127;
                                out[((bb*HID + h)*128 + y)*128 + x] = hn;
                            } else {
                                ivec[c][CC + h] = hn;
                            }
                        }
                    }
                }
                // next iteration's stage barrier orders h writes vs reads
            }
            __syncthreads();   // done with slen/soff/ivec before next grp reload
        }
    } else {
        // ---------------- singleton chains (FFMA2) ----------------
        int lane = tid & 31, warp = tid >> 5;       // 8 warps
        int sidx = blockIdx.x - MUL_BLOCKS;
        int bb = sidx & 7;
        int sg = sidx >> 3;                         // 0..20
        int ns = g_ns[bb];

        for (int i = tid; i < CC*GATES; i += 256) Ws[i] = g_WT[i];
        for (int i = tid; i < GATES; i += 256) bs[i] = g_bias[i];
        __syncthreads();

        for (int base = sg*32; base < ns; base += (SGL_BLOCKS/8)*32) {
            int idx0 = base + (warp << 2);
            if (idx0 >= ns) continue;

            int rec = -1;
            if (lane < 4 && idx0 + lane < ns) rec = g_single[bb*NN + idx0 + lane];
            __syncwarp();
            #pragma unroll
            for (int s2 = 0; s2 < 2; s2++) {
                int slot = lane + (s2 << 5);
                int c = slot >> 4, k = slot & 15;
                int rc = __shfl_sync(0xffffffffu, rec, c);
                if (rc >= 0) {
                    int ev = rc & 2047;
                    xsh[warp][c][k] = feat[(bb*NN + ev)*CC + k];
                }
            }
            __syncwarp();

            // acc pairs: acc2[c][2q+p] = gates q*128 + lane*4 + 2p + {0,1}
            unsigned long long acc2[4][8];
            #pragma unroll
            for (int q = 0; q < 4; q++) {
                ulonglong2 bq = *(const ulonglong2*)&bs[q*128 + (lane << 2)];
                #pragma unroll
                for (int c = 0; c < 4; c++) {
                    acc2[c][2*q]   = bq.x;
                    acc2[c][2*q+1] = bq.y;
                }
            }
            #pragma unroll 4
            for (int k = 0; k < CC; k++) {
                const ulonglong2* wp = (const ulonglong2*)&Ws[k*GATES + (lane << 2)];
                ulonglong2 w0 = wp[0];
                ulonglong2 w1 = wp[32];
                ulonglong2 w2 = wp[64];
                ulonglong2 w3 = wp[96];
                #pragma unroll
                for (int c = 0; c < 4; c++) {
                    unsigned long long iv2 = dup2_(xsh[warp][c][k]);
                    fma2_(acc2[c][0], iv2, w0.x); fma2_(acc2[c][1], iv2, w0.y);
                    fma2_(acc2[c][2], iv2, w1.x); fma2_(acc2[c][3], iv2, w1.y);
                    fma2_(acc2[c][4], iv2, w2.x); fma2_(acc2[c][5], iv2, w2.y);
                    fma2_(acc2[c][6], iv2, w3.x); fma2_(acc2[c][7], iv2, w3.y);
                }
            }
            #pragma unroll
            for (int c = 0; c < 4; c++) {
                int rc = __shfl_sync(0xffffffffu, rec, c);
                if (rc >= 0) {
                    int rf = rc >> 11;
                    int y = rf >> 7, x = rf & 127;
                    float2 i0 = unpack2_(acc2[c][0]), i1 = unpack2_(acc2[c][1]);
                    float2 g0 = unpack2_(acc2[c][4]), g1 = unpack2_(acc2[c][5]);
                    float2 o0 = unpack2_(acc2[c][6]), o1 = unpack2_(acc2[c][7]);
                    float gi[4] = {i0.x, i0.y, i1.x, i1.y};
                    float gg[4] = {g0.x, g0.y, g1.x, g1.y};
                    float go[4] = {o0.x, o0.y, o1.x, o1.y};
                    #pragma unroll
                    for (int i = 0; i < 4; i++) {
                        float cn = sigmoidf_(gi[i]) * tanhf_(gg[i]);   // c_prev=0, f dead
                        float hh = sigmoidf_(go[i]) * tanhf_(cn);
                        out[((bb*HID + (lane << 2) + i)*128 + y)*128 + x] = hh;
                    }
                }
            }
        }
    }
}

extern "C" void kernel_launch(void* const* d_in, const int* in_sizes, int n_in,
                              void* d_out, int out_size) {
    const float* features = (const float*)d_in[0];
    const int*   coords   = (const int*)  d_in[1];
    const float* w_ih     = (const float*)d_in[2];
    const float* w_hh     = (const float*)d_in[3];
    const float* b_ih     = (const float*)d_in[4];
    const float* b_hh     = (const float*)d_in[5];
    float* out = (float*)d_out;

    k_prep<<<PREP_GRID, 1024>>>((float4*)out, coords, w_ih, w_hh, b_ih, b_hh);
    k_lstm<<<LSTM_GRID, 256>>>(features, out);
}